// round 11
// baseline (speedup 1.0000x reference)
#include <cuda_runtime.h>
#include <cuda_bf16.h>

// Problem dims (fixed)
#define BB 64
#define PP 196
#define ENC 2048
#define LL 20
#define TT 19
#define VV 32000
#define HH 512
#define EE 512
#define AA 512

#define PRED_SZ ((size_t)BB * TT * VV)
#define ALPHA_SZ ((size_t)BB * TT * PP)

// FFMA GEMM tile config (init kernel)
#define TM 64
#define TN 128
#define TK 16
#define SP_INIT 8
#define SP_GT   8   // gates K=3072 -> chunks of 384 (12 mma-chunks)

// ---------------- scratch (device globals; no allocation) ----------------
__device__ int   g_sidx[BB];
__device__ int   g_dlen[BB];
__device__ int   g_ystride;
__device__ float g_mean[BB * ENC];
__device__ float g_h[BB * HH];
__device__ float g_c[BB * HH];
__device__ float g_att1[BB * PP * AA];
__device__ float g_alpha[BB * PP];
__device__ float g_att2F[BB * AA];
__device__ float g_gateF[BB * ENC];
__device__ float g_initP[SP_INIT * BB * 1024];
__device__ float g_gatesP[SP_GT * BB * 4 * HH];

// pre-split bf16 hi/lo packed (2 bf16 per unsigned, K-pairs)
__device__ unsigned g_fcWh[VV * 256],  g_fcWl[VV * 256];     // fc_W   [32000][512]
__device__ unsigned g_embh[VV * 256],  g_embl[VV * 256];     // embed  [32000][512]
__device__ unsigned g_gWh[2048 * 1536], g_gWl[2048 * 1536];  // [Wih|Whh] [2048][3072]
__device__ unsigned g_hWh[2560 * 256], g_hWl[2560 * 256];    // [h2aW;fbW] [2560][512]
__device__ unsigned g_e2h[512 * 1024], g_e2l[512 * 1024];    // e2aW [512][2048]
__device__ unsigned g_hbh[BB * 256],  g_hbl[BB * 256];       // h split
__device__ unsigned g_cxh[BB * 1024], g_cxl[BB * 1024];      // ctx split

__device__ __forceinline__ float sigmf(float x) { return 1.0f / (1.0f + expf(-x)); }

#define LD4(p)  (*(const float4*)&(p))
#define LDU4(p) (*(const uint4*)&(p))

__device__ __forceinline__ void split2(float x0, float x1, unsigned& hi, unsigned& lo) {
    __nv_bfloat16 h0 = __float2bfloat16_rn(x0);
    __nv_bfloat16 h1 = __float2bfloat16_rn(x1);
    __nv_bfloat16 l0 = __float2bfloat16_rn(x0 - __bfloat162float(h0));
    __nv_bfloat16 l1 = __float2bfloat16_rn(x1 - __bfloat162float(h1));
    hi = ((unsigned)__bfloat16_as_ushort(h1) << 16) | __bfloat16_as_ushort(h0);
    lo = ((unsigned)__bfloat16_as_ushort(l1) << 16) | __bfloat16_as_ushort(l0);
}

__device__ __forceinline__ void mma_bf16(float c[4], unsigned a0, unsigned a1,
                                         unsigned a2, unsigned a3,
                                         unsigned b0, unsigned b1) {
    asm volatile(
        "mma.sync.aligned.m16n8k16.row.col.f32.bf16.bf16.f32 "
        "{%0,%1,%2,%3},{%4,%5,%6,%7},{%8,%9},{%0,%1,%2,%3};"
        : "+f"(c[0]), "+f"(c[1]), "+f"(c[2]), "+f"(c[3])
        : "r"(a0), "r"(a1), "r"(a2), "r"(a3), "r"(b0), "r"(b1));
}

// ---------------- MMA core v2: staging passed as statements ----------------
// Exposes: tid,n0,warp,lane,mw,nh,g,tig,ar,aq,br,bq, c[8][4]. kc2 = u32 chunk base.
#define MMA_CORE2(ASTAGE, BSTAGE, KC2START, NCHUNKS, TMASK)                     \
    __shared__ unsigned sAh[64][17], sAl[64][17];                               \
    __shared__ unsigned sBh[128][17], sBl[128][17];                             \
    int tid = threadIdx.x;                                                      \
    int n0 = blockIdx.x * 128;                                                  \
    int warp = tid >> 5, lane = tid & 31;                                       \
    int mw = warp >> 1, nh = warp & 1;                                          \
    int g = lane >> 2, tig = lane & 3;                                          \
    int ar = tid >> 2, aq = tid & 3;                                            \
    int br = tid >> 1, bq = tid & 1;                                            \
    int myact = (g_dlen[mw * 16] > (TMASK));                                    \
    float c[8][4];                                                              \
    _Pragma("unroll")                                                           \
    for (int i = 0; i < 8; ++i) c[i][0] = c[i][1] = c[i][2] = c[i][3] = 0.f;    \
    for (int ch = 0; ch < (NCHUNKS); ++ch) {                                    \
        int kc2 = (KC2START) + ch * 16;                                         \
        ASTAGE;                                                                 \
        BSTAGE;                                                                 \
        __syncthreads();                                                        \
        if (myact) {                                                            \
            _Pragma("unroll")                                                   \
            for (int ks = 0; ks < 2; ++ks) {                                    \
                int kb = ks * 8;                                                \
                int r0 = mw * 16 + g, r1 = r0 + 8;                              \
                unsigned a0 = sAh[r0][kb+tig],   a1 = sAh[r1][kb+tig];          \
                unsigned a2 = sAh[r0][kb+4+tig], a3 = sAh[r1][kb+4+tig];        \
                unsigned l0 = sAl[r0][kb+tig],   l1 = sAl[r1][kb+tig];          \
                unsigned l2 = sAl[r0][kb+4+tig], l3 = sAl[r1][kb+4+tig];        \
                _Pragma("unroll")                                               \
                for (int nt = 0; nt < 8; ++nt) {                                \
                    int colr = nh * 64 + nt * 8 + g;                            \
                    unsigned b0 = sBh[colr][kb+tig], b1 = sBh[colr][kb+4+tig];  \
                    unsigned lb0 = sBl[colr][kb+tig], lb1 = sBl[colr][kb+4+tig];\
                    mma_bf16(c[nt], a0, a1, a2, a3, b0, b1);                    \
                    mma_bf16(c[nt], l0, l1, l2, l3, b0, b1);                    \
                    mma_bf16(c[nt], a0, a1, a2, a3, lb0, lb1);                  \
                }                                                               \
            }                                                                   \
        }                                                                       \
        __syncthreads();                                                        \
    }

// B-stage from pre-split arrays, row stride RS (u32), rows n0+br
#define BSTAGE_PRE(BH, BL, RS)                                                  \
    {                                                                           \
        int k2 = kc2 + bq * 8;                                                  \
        const unsigned* ph = (BH) + (size_t)(n0 + br) * (RS) + k2;              \
        const unsigned* pl = (BL) + (size_t)(n0 + br) * (RS) + k2;              \
        uint4 u0 = LDU4(ph[0]), u1 = LDU4(ph[4]);                               \
        uint4 v0 = LDU4(pl[0]), v1 = LDU4(pl[4]);                               \
        sBh[br][bq*8+0]=u0.x; sBh[br][bq*8+1]=u0.y; sBh[br][bq*8+2]=u0.z; sBh[br][bq*8+3]=u0.w; \
        sBh[br][bq*8+4]=u1.x; sBh[br][bq*8+5]=u1.y; sBh[br][bq*8+6]=u1.z; sBh[br][bq*8+7]=u1.w; \
        sBl[br][bq*8+0]=v0.x; sBl[br][bq*8+1]=v0.y; sBl[br][bq*8+2]=v0.z; sBl[br][bq*8+3]=v0.w; \
        sBl[br][bq*8+4]=v1.x; sBl[br][bq*8+5]=v1.y; sBl[br][bq*8+6]=v1.z; sBl[br][bq*8+7]=v1.w; \
    }

// A-stage from pre-split h buffers (rows = ar directly)
#define ASTAGE_H                                                                \
    {                                                                           \
        int k2 = kc2 + aq * 4;                                                  \
        uint4 u = LDU4(g_hbh[ar * 256 + k2]);                                   \
        uint4 v = LDU4(g_hbl[ar * 256 + k2]);                                   \
        sAh[ar][aq*4+0]=u.x; sAh[ar][aq*4+1]=u.y; sAh[ar][aq*4+2]=u.z; sAh[ar][aq*4+3]=u.w; \
        sAl[ar][aq*4+0]=v.x; sAl[ar][aq*4+1]=v.y; sAl[ar][aq*4+2]=v.z; sAl[ar][aq*4+3]=v.w; \
    }

// ---------------- FFMA GEMM body (init only) ----------------
#define GEMM2_BODY(AFETCH4, WFETCH4, KSTART, KTILES)                            \
    __shared__ float As[2][TK][TM + 4];                                         \
    __shared__ float Ws[2][TK][TN + 4];                                         \
    int tid = threadIdx.x;                                                      \
    int tx = tid & 31, ty = tid >> 5;                                           \
    int n0 = blockIdx.x * TN;                                                   \
    int arow = tid >> 2, kq = tid & 3;                                          \
    int brow0 = tid >> 2, brow1 = (tid >> 2) + 64;                              \
    float acc[8][4] = {};                                                       \
    float4 rA, rB0, rB1;                                                        \
    {                                                                           \
        int k = (KSTART) + kq * 4;                                              \
        rA = AFETCH4(arow, k);                                                  \
        rB0 = WFETCH4(brow0, k);                                                \
        rB1 = WFETCH4(brow1, k);                                                \
    }                                                                           \
    As[0][kq * 4 + 0][arow] = rA.x;  As[0][kq * 4 + 1][arow] = rA.y;            \
    As[0][kq * 4 + 2][arow] = rA.z;  As[0][kq * 4 + 3][arow] = rA.w;            \
    Ws[0][kq * 4 + 0][brow0] = rB0.x; Ws[0][kq * 4 + 1][brow0] = rB0.y;         \
    Ws[0][kq * 4 + 2][brow0] = rB0.z; Ws[0][kq * 4 + 3][brow0] = rB0.w;         \
    Ws[0][kq * 4 + 0][brow1] = rB1.x; Ws[0][kq * 4 + 1][brow1] = rB1.y;         \
    Ws[0][kq * 4 + 2][brow1] = rB1.z; Ws[0][kq * 4 + 3][brow1] = rB1.w;         \
    __syncthreads();                                                            \
    for (int tile = 0; tile < (KTILES); ++tile) {                               \
        int buf = tile & 1;                                                     \
        bool more = (tile + 1) < (KTILES);                                      \
        if (more) {                                                             \
            int k = (KSTART) + (tile + 1) * TK + kq * 4;                        \
            rA = AFETCH4(arow, k);                                              \
            rB0 = WFETCH4(brow0, k);                                            \
            rB1 = WFETCH4(brow1, k);                                            \
        }                                                                       \
        _Pragma("unroll")                                                       \
        for (int kk = 0; kk < TK; ++kk) {                                       \
            float4 a0 = *(const float4*)&As[buf][kk][ty * 8];                   \
            float4 a1 = *(const float4*)&As[buf][kk][ty * 8 + 4];               \
            float4 wv = *(const float4*)&Ws[buf][kk][tx * 4];                   \
            float av[8] = {a0.x, a0.y, a0.z, a0.w, a1.x, a1.y, a1.z, a1.w};     \
            float wr[4] = {wv.x, wv.y, wv.z, wv.w};                             \
            _Pragma("unroll")                                                   \
            for (int i = 0; i < 8; ++i)                                         \
                _Pragma("unroll")                                               \
                for (int j = 0; j < 4; ++j) acc[i][j] += av[i] * wr[j];         \
        }                                                                       \
        __syncthreads();                                                        \
        if (more) {                                                             \
            int nb = buf ^ 1;                                                   \
            As[nb][kq * 4 + 0][arow] = rA.x;  As[nb][kq * 4 + 1][arow] = rA.y;  \
            As[nb][kq * 4 + 2][arow] = rA.z;  As[nb][kq * 4 + 3][arow] = rA.w;  \
            Ws[nb][kq * 4 + 0][brow0] = rB0.x; Ws[nb][kq * 4 + 1][brow0] = rB0.y;\
            Ws[nb][kq * 4 + 2][brow0] = rB0.z; Ws[nb][kq * 4 + 3][brow0] = rB0.w;\
            Ws[nb][kq * 4 + 0][brow1] = rB1.x; Ws[nb][kq * 4 + 1][brow1] = rB1.y;\
            Ws[nb][kq * 4 + 2][brow1] = rB1.z; Ws[nb][kq * 4 + 3][brow1] = rB1.w;\
            __syncthreads();                                                    \
        }                                                                       \
    }

// ---------------- weight split kernels (preamble, once) ----------------
__global__ void k_split(const float* __restrict__ s, unsigned* __restrict__ dh,
                        unsigned* __restrict__ dl, int n2) {
    int i = blockIdx.x * 256 + threadIdx.x;
    if (i < n2) {
        float2 v = *(const float2*)&s[2 * (size_t)i];
        unsigned h, l; split2(v.x, v.y, h, l);
        dh[i] = h; dl[i] = l;
    }
}
// concat along K: row r = [A(r, 0..ka) | B(r, 0..kb)]
__global__ void k_split_cat(const float* __restrict__ Asrc, int ka,
                            const float* __restrict__ Bsrc, int kb,
                            unsigned* __restrict__ dh, unsigned* __restrict__ dl,
                            int rows) {
    int K2 = (ka + kb) >> 1;
    int i = blockIdx.x * 256 + threadIdx.x;
    if (i < rows * K2) {
        int r = i / K2, k = (i % K2) * 2;
        float x0, x1;
        if (k < ka) { x0 = Asrc[(size_t)r * ka + k]; x1 = Asrc[(size_t)r * ka + k + 1]; }
        else { x0 = Bsrc[(size_t)r * kb + k - ka]; x1 = Bsrc[(size_t)r * kb + k - ka + 1]; }
        unsigned h, l; split2(x0, x1, h, l);
        dh[i] = h; dl[i] = l;
    }
}

// ---------------- sort / layout detect ----------------
__global__ void k_sort(const int* __restrict__ y32, float* __restrict__ out, size_t cap) {
    __shared__ int len[BB];
    __shared__ int stride_s;
    int i = threadIdx.x;
    if (i == 0) {
        int odd = 0;
        for (int l = 0; l < LL; ++l) odd |= (y32[2 * l + 1] != 0);
        stride_s = odd ? 1 : 2;
        g_ystride = stride_s;
    }
    __syncthreads();
    int stride = stride_s;
    if (i < BB) {
        int c = 0;
        for (int l = 0; l < LL; ++l) c += (y32[(i * LL + l) * stride] != 0);
        len[i] = c;
    }
    __syncthreads();
    if (i < BB) {
        int r = 0;
        for (int j = 0; j < BB; ++j)
            r += (len[j] > len[i]) || (len[j] == len[i] && j < i);
        g_sidx[r] = i;
        g_dlen[r] = len[i] - 1;
        size_t base = PRED_SZ + ALPHA_SZ;
        if (base + r < cap)      out[base + r]      = (float)(len[i] - 1);
        if (base + BB + r < cap) out[base + BB + r] = (float)i;
    }
}

// ---------------- mean over P ----------------
__global__ void k_mean(const float* __restrict__ enc) {
    int b = blockIdx.x;
    int e = blockIdx.y * 256 + threadIdx.x;
    const float* base = enc + (size_t)g_sidx[b] * PP * ENC + e;
    float s = 0.f;
    #pragma unroll 8
    for (int p = 0; p < PP; ++p) s += base[p * ENC];
    g_mean[b * ENC + e] = s * (1.0f / PP);
}

// ---------------- init h0/c0 GEMM + reduce (also emits h bf split) ----------------
__global__ __launch_bounds__(256) void k_init_gemm(const float* __restrict__ ihW,
                                                   const float* __restrict__ icW) {
    int z = blockIdx.z;
#define A_INIT(row, k) LD4(g_mean[(row) * ENC + (k)])
#define W_INIT(row, k) ((n0 + (row)) < HH ? LD4(ihW[(n0 + (row)) * ENC + (k)]) \
                                          : LD4(icW[(n0 + (row) - HH) * ENC + (k)]))
    GEMM2_BODY(A_INIT, W_INIT, z * (ENC / SP_INIT), (ENC / SP_INIT) / TK);
    float* P = g_initP + (size_t)z * BB * 1024;
    #pragma unroll
    for (int i = 0; i < 8; ++i) {
        int m = ty * 8 + i;
        *(float4*)&P[m * 1024 + n0 + tx * 4] =
            make_float4(acc[i][0], acc[i][1], acc[i][2], acc[i][3]);
    }
#undef A_INIT
#undef W_INIT
}

__global__ void k_init_red(const float* __restrict__ ihb, const float* __restrict__ icb) {
    int b = blockIdx.x, t2 = threadIdx.x;   // 256 threads
    float hv[2];
    #pragma unroll
    for (int q = 0; q < 2; ++q) {
        int n = 2 * t2 + q;
        float sh = ihb[n], sc = icb[n];
        #pragma unroll
        for (int z = 0; z < SP_INIT; ++z) {
            const float* P = g_initP + ((size_t)z * BB + b) * 1024;
            sh += P[n];
            sc += P[512 + n];
        }
        g_h[b * HH + n] = sh;
        g_c[b * HH + n] = sc;
        hv[q] = sh;
    }
    unsigned hh, ll; split2(hv[0], hv[1], hh, ll);
    g_hbh[b * 256 + t2] = hh;
    g_hbl[b * 256 + t2] = ll;
}

// ---------------- att1 (MMA): enc_sorted @ e2aW^T ----------------
__global__ __launch_bounds__(256) void k_att1_mma(const float* __restrict__ enc) {
    __shared__ int rowOff[64];
    int m0 = blockIdx.y * 64;
    if (threadIdx.x < 64) {
        int m = m0 + threadIdx.x;
        int b = m / PP, p = m % PP;
        rowOff[threadIdx.x] = (g_sidx[b] * PP + p) * ENC;
    }
    __syncthreads();
#define ASTAGE_ENC                                                              \
    {                                                                           \
        int ka = 2 * kc2 + aq * 8;                                              \
        float4 f0 = LD4(enc[rowOff[ar] + ka]);                                  \
        float4 f1 = LD4(enc[rowOff[ar] + ka + 4]);                              \
        unsigned hi, lo;                                                        \
        split2(f0.x, f0.y, hi, lo); sAh[ar][aq*4+0]=hi; sAl[ar][aq*4+0]=lo;     \
        split2(f0.z, f0.w, hi, lo); sAh[ar][aq*4+1]=hi; sAl[ar][aq*4+1]=lo;     \
        split2(f1.x, f1.y, hi, lo); sAh[ar][aq*4+2]=hi; sAl[ar][aq*4+2]=lo;     \
        split2(f1.z, f1.w, hi, lo); sAh[ar][aq*4+3]=hi; sAl[ar][aq*4+3]=lo;     \
    }
    MMA_CORE2(ASTAGE_ENC, BSTAGE_PRE(g_e2h, g_e2l, 1024), 0, ENC / 32, -1);
    #pragma unroll
    for (int nt = 0; nt < 8; ++nt) {
        int col = n0 + nh * 64 + nt * 8 + 2 * tig;
        int r0 = mw * 16 + g, r1 = r0 + 8;
        g_att1[(size_t)(m0 + r0) * AA + col]     = c[nt][0];
        g_att1[(size_t)(m0 + r0) * AA + col + 1] = c[nt][1];
        g_att1[(size_t)(m0 + r1) * AA + col]     = c[nt][2];
        g_att1[(size_t)(m0 + r1) * AA + col + 1] = c[nt][3];
    }
#undef ASTAGE_ENC
}

// ---------------- hW (MMA): h @ [h2aW;fbW]^T -> att2F + gateF(sigmoid) ----------------
__global__ __launch_bounds__(256) void k_hw(const float* __restrict__ fbb, int t) {
    MMA_CORE2(ASTAGE_H, BSTAGE_PRE(g_hWh, g_hWl, 256), 0, HH / 32, t);
    #pragma unroll
    for (int nt = 0; nt < 8; ++nt) {
        int col = n0 + nh * 64 + nt * 8 + 2 * tig;
        int r0 = mw * 16 + g, r1 = r0 + 8;
        float v[4] = {c[nt][0], c[nt][1], c[nt][2], c[nt][3]};
        int rr[4] = {r0, r0, r1, r1};
        int cc[4] = {col, col + 1, col, col + 1};
        #pragma unroll
        for (int q = 0; q < 4; ++q) {
            if (cc[q] < AA) g_att2F[rr[q] * AA + cc[q]] = v[q];
            else {
                int e = cc[q] - AA;
                g_gateF[rr[q] * ENC + e] = sigmf(v[q] + fbb[e]);
            }
        }
    }
}

// ---------------- score + softmax + alpha ----------------
__global__ __launch_bounds__(512) void k_score(const float* __restrict__ attW,
                                               const float* __restrict__ attb,
                                               float* __restrict__ out, size_t cap, int t) {
    __shared__ float a2[AA];
    __shared__ float aw[AA];
    __shared__ float sc[PP];
    __shared__ float red[2];
    int b = blockIdx.x, tid = threadIdx.x;
    if (g_dlen[b] <= t) {
        for (int p = tid; p < PP; p += 512) {
            size_t idx = PRED_SZ + (size_t)(b * TT + t) * PP + p;
            if (idx < cap) out[idx] = 0.f;
        }
        return;
    }
    for (int i = tid; i < AA; i += 512) {
        a2[i] = g_att2F[b * AA + i];
        aw[i] = attW[i];
    }
    __syncthreads();
    int w = tid >> 5, lane = tid & 31;
    for (int p = w; p < PP; p += 16) {
        const float* base = g_att1 + (size_t)(b * PP + p) * AA;
        float s = 0.f;
        #pragma unroll 4
        for (int a0 = lane; a0 < AA; a0 += 32) {
            float v = base[a0] + a2[a0];
            s += fmaxf(v, 0.f) * aw[a0];
        }
        #pragma unroll
        for (int o = 16; o; o >>= 1) s += __shfl_down_sync(0xFFFFFFFFu, s, o);
        if (lane == 0) sc[p] = s + attb[0];
    }
    __syncthreads();
    if (w == 0) {
        float mx = -1e30f;
        for (int p = lane; p < PP; p += 32) mx = fmaxf(mx, sc[p]);
        #pragma unroll
        for (int o = 16; o; o >>= 1) mx = fmaxf(mx, __shfl_xor_sync(0xFFFFFFFFu, mx, o));
        float sm = 0.f;
        for (int p = lane; p < PP; p += 32) sm += expf(sc[p] - mx);
        #pragma unroll
        for (int o = 16; o; o >>= 1) sm += __shfl_xor_sync(0xFFFFFFFFu, sm, o);
        if (lane == 0) { red[0] = mx; red[1] = 1.0f / sm; }
    }
    __syncthreads();
    float mx = red[0], inv = red[1];
    for (int p = tid; p < PP; p += 512) {
        float al = expf(sc[p] - mx) * inv;
        g_alpha[b * PP + p] = al;
        size_t idx = PRED_SZ + (size_t)(b * TT + t) * PP + p;
        if (idx < cap) out[idx] = al;
    }
}

// ---------------- ctx: gate * (alpha @ enc), emits packed bf split ----------------
__global__ void k_ctx(const float* __restrict__ enc, int t) {
    __shared__ float al[PP];
    int b = blockIdx.x;
    if (g_dlen[b] <= t) return;
    int tid = threadIdx.x;               // 256
    int e0 = blockIdx.y * 512 + 2 * tid;
    if (tid < PP) al[tid] = g_alpha[b * PP + tid];
    __syncthreads();
    const float* base = enc + (size_t)g_sidx[b] * PP * ENC + e0;
    float s0 = 0.f, s1 = 0.f;
    #pragma unroll 4
    for (int p = 0; p < PP; ++p) {
        float2 v = *(const float2*)&base[p * ENC];
        s0 += al[p] * v.x;
        s1 += al[p] * v.y;
    }
    float2 gt = *(const float2*)&g_gateF[b * ENC + e0];
    unsigned h, l; split2(gt.x * s0, gt.y * s1, h, l);
    int k2 = e0 >> 1;
    g_cxh[b * 1024 + k2] = h;
    g_cxl[b * 1024 + k2] = l;
}

// ---------------- gates (MMA): [emb|ctx|h]bf @ gW^T, K-split x8 ----------------
__global__ __launch_bounds__(256) void k_gates_mma(const int* __restrict__ y32, int t) {
    __shared__ int tok2Off[64];
    if (threadIdx.x < 64) {
        int tok = y32[(g_sidx[threadIdx.x] * LL + t) * g_ystride];
        tok = max(0, min(tok, VV - 1));
        tok2Off[threadIdx.x] = tok * 256;
    }
    __syncthreads();
    int z = blockIdx.z;
#define ASTAGE_GT                                                               \
    {                                                                           \
        int k2 = kc2 + aq * 4;                                                  \
        const unsigned *ph, *pl;                                                \
        if (k2 < 256)       { ph = g_embh + tok2Off[ar] + k2;                   \
                              pl = g_embl + tok2Off[ar] + k2; }                 \
        else if (k2 < 1280) { ph = g_cxh + ar * 1024 + (k2 - 256);              \
                              pl = g_cxl + ar * 1024 + (k2 - 256); }            \
        else                { ph = g_hbh + ar * 256 + (k2 - 1280);              \
                              pl = g_hbl + ar * 256 + (k2 - 1280); }            \
        uint4 u = LDU4(ph[0]);                                                  \
        uint4 v = LDU4(pl[0]);                                                  \
        sAh[ar][aq*4+0]=u.x; sAh[ar][aq*4+1]=u.y; sAh[ar][aq*4+2]=u.z; sAh[ar][aq*4+3]=u.w; \
        sAl[ar][aq*4+0]=v.x; sAl[ar][aq*4+1]=v.y; sAl[ar][aq*4+2]=v.z; sAl[ar][aq*4+3]=v.w; \
    }
    MMA_CORE2(ASTAGE_GT, BSTAGE_PRE(g_gWh, g_gWl, 1536), z * 192, 12, t);
    float* P = g_gatesP + (size_t)z * BB * 4 * HH;
    #pragma unroll
    for (int nt = 0; nt < 8; ++nt) {
        int col = n0 + nh * 64 + nt * 8 + 2 * tig;
        int r0 = mw * 16 + g, r1 = r0 + 8;
        P[r0 * (4 * HH) + col]     = c[nt][0];
        P[r0 * (4 * HH) + col + 1] = c[nt][1];
        P[r1 * (4 * HH) + col]     = c[nt][2];
        P[r1 * (4 * HH) + col + 1] = c[nt][3];
    }
#undef ASTAGE_GT
}

// ---------------- LSTM: reduce partials, update h/c, emit h bf split ----------------
__global__ void k_lstm(const float* __restrict__ bih, const float* __restrict__ bhh, int t) {
    int b = blockIdx.x, t2 = threadIdx.x;   // 256 threads
    if (g_dlen[b] <= t) return;
    float hv[2];
    #pragma unroll
    for (int q = 0; q < 2; ++q) {
        int j = 2 * t2 + q;
        float gs[4];
        #pragma unroll
        for (int gI = 0; gI < 4; ++gI) {
            int n = gI * HH + j;
            float s = bih[n] + bhh[n];
            #pragma unroll
            for (int z = 0; z < SP_GT; ++z)
                s += g_gatesP[((size_t)z * BB + b) * (4 * HH) + n];
            gs[gI] = s;
        }
        float ig = sigmf(gs[0]);
        float fg = sigmf(gs[1]);
        float gg = tanhf(gs[2]);
        float og = sigmf(gs[3]);
        float cv = fg * g_c[b * HH + j] + ig * gg;
        g_c[b * HH + j] = cv;
        float h = og * tanhf(cv);
        g_h[b * HH + j] = h;
        hv[q] = h;
    }
    unsigned hh, ll; split2(hv[0], hv[1], hh, ll);
    g_hbh[b * 256 + t2] = hh;
    g_hbl[b * 256 + t2] = ll;
}

// ---------------- logits (MMA) + masked bounded write ----------------
__global__ __launch_bounds__(256) void k_logits_mma(const float* __restrict__ fcb,
                                                    float* __restrict__ out, size_t cap, int t) {
    MMA_CORE2(ASTAGE_H, BSTAGE_PRE(g_fcWh, g_fcWl, 256), 0, HH / 32, t);
    #pragma unroll
    for (int nt = 0; nt < 8; ++nt) {
        int col = n0 + nh * 64 + nt * 8 + 2 * tig;
        int r0 = mw * 16 + g, r1 = r0 + 8;
        bool act0 = g_dlen[r0] > t, act1 = g_dlen[r1] > t;
        size_t i00 = ((size_t)r0 * TT + t) * VV + col;
        size_t i10 = ((size_t)r1 * TT + t) * VV + col;
        if (i00 + 1 < cap) {
            out[i00]     = act0 ? c[nt][0] + fcb[col]     : 0.f;
            out[i00 + 1] = act0 ? c[nt][1] + fcb[col + 1] : 0.f;
        }
        if (i10 + 1 < cap) {
            out[i10]     = act1 ? c[nt][2] + fcb[col]     : 0.f;
            out[i10 + 1] = act1 ? c[nt][3] + fcb[col + 1] : 0.f;
        }
    }
}

// ---------------- launch ----------------
extern "C" void kernel_launch(void* const* d_in, const int* in_sizes, int n_in,
                              void* d_out, int out_size) {
    if (n_in < 19) return;
    const float* enc  = (const float*)d_in[0];
    const int*   y32  = (const int*)d_in[1];
    const float* emb  = (const float*)d_in[2];
    const float* e2aW = (const float*)d_in[3];
    const float* h2aW = (const float*)d_in[4];
    const float* attW = (const float*)d_in[5];
    const float* attb = (const float*)d_in[6];
    const float* fbW  = (const float*)d_in[7];
    const float* fbb  = (const float*)d_in[8];
    const float* Wih  = (const float*)d_in[9];
    const float* bih  = (const float*)d_in[10];
    const float* Whh  = (const float*)d_in[11];
    const float* bhh  = (const float*)d_in[12];
    const float* fcW  = (const float*)d_in[13];
    const float* fcb  = (const float*)d_in[14];
    const float* ihW  = (const float*)d_in[15];
    const float* ihb  = (const float*)d_in[16];
    const float* icW  = (const float*)d_in[17];
    const float* icb  = (const float*)d_in[18];

    float* out = (float*)d_out;
    size_t cap = (size_t)out_size;

    unsigned *p_fcWh, *p_fcWl, *p_embh, *p_embl, *p_e2h, *p_e2l;
    unsigned *p_gWh, *p_gWl, *p_hWh, *p_hWl;
    cudaGetSymbolAddress((void**)&p_fcWh, g_fcWh);
    cudaGetSymbolAddress((void**)&p_fcWl, g_fcWl);
    cudaGetSymbolAddress((void**)&p_embh, g_embh);
    cudaGetSymbolAddress((void**)&p_embl, g_embl);
    cudaGetSymbolAddress((void**)&p_e2h,  g_e2h);
    cudaGetSymbolAddress((void**)&p_e2l,  g_e2l);
    cudaGetSymbolAddress((void**)&p_gWh,  g_gWh);
    cudaGetSymbolAddress((void**)&p_gWl,  g_gWl);
    cudaGetSymbolAddress((void**)&p_hWh,  g_hWh);
    cudaGetSymbolAddress((void**)&p_hWl,  g_hWl);

    // preamble
    k_sort<<<1, 64>>>(y32, out, cap);
    k_mean<<<dim3(BB, ENC / 256), 256>>>(enc);
    k_init_gemm<<<dim3(1024 / TN, 1, SP_INIT), 256>>>(ihW, icW);
    k_init_red<<<BB, 256>>>(ihb, icb);

    // weight splits (once per launch)
    k_split<<<(VV * 256 + 255) / 256, 256>>>(fcW, p_fcWh, p_fcWl, VV * 256);
    k_split<<<(VV * 256 + 255) / 256, 256>>>(emb, p_embh, p_embl, VV * 256);
    k_split<<<(512 * 1024 + 255) / 256, 256>>>(e2aW, p_e2h, p_e2l, 512 * 1024);
    k_split_cat<<<(2048 * 1536 + 255) / 256, 256>>>(Wih, EE + ENC, Whh, HH,
                                                    p_gWh, p_gWl, 2048);
    k_split<<<(512 * 256 + 255) / 256, 256>>>(h2aW, p_hWh, p_hWl, 512 * 256);
    k_split<<<(2048 * 256 + 255) / 256, 256>>>(fbW, p_hWh + 512 * 256,
                                               p_hWl + 512 * 256, 2048 * 256);

    k_att1_mma<<<dim3(AA / 128, (BB * PP) / 64), 256>>>(enc);

    for (int t = 0; t < TT; ++t) {
        k_hw<<<2560 / 128, 256>>>(fbb, t);
        k_score<<<BB, 512>>>(attW, attb, out, cap, t);
        k_ctx<<<dim3(BB, 4), 256>>>(enc, t);
        k_gates_mma<<<dim3((4 * HH) / 128, 1, SP_GT), 256>>>(y32, t);
        k_lstm<<<BB, 256>>>(bih, bhh, t);
        k_logits_mma<<<VV / 128, 256>>>(fcb, out, cap, t);
    }
}

// round 12
// speedup vs baseline: 1.0403x; 1.0403x over previous
#include <cuda_runtime.h>
#include <cuda_bf16.h>

// Problem dims (fixed)
#define BB 64
#define PP 196
#define ENC 2048
#define LL 20
#define TT 19
#define VV 32000
#define HH 512
#define EE 512
#define AA 512

#define PRED_SZ ((size_t)BB * TT * VV)
#define ALPHA_SZ ((size_t)BB * TT * PP)

// FFMA GEMM tile config (init kernel)
#define TM 64
#define TN 128
#define TK 16
#define SP_INIT 8
#define SP_GT   8

// smem layout for MMA pipe (u32 words): per buffer 6528 = Ah(1088)+Al(1088)+Bh(2176)+Bl(2176)
#define SM_BUF   6528
#define SM_AL    1088
#define SM_BH    2176
#define SM_BL    4352
#define SM_BYTES (2 * SM_BUF * 4)

// ---------------- scratch (device globals; no allocation) ----------------
__device__ int   g_sidx[BB];
__device__ int   g_dlen[BB];
__device__ int   g_ystride;
__device__ float g_mean[BB * ENC];
__device__ float g_h[BB * HH];
__device__ float g_c[BB * HH];
__device__ float g_att1[BB * PP * AA];
__device__ float g_alpha[BB * PP];
__device__ float g_att2F[BB * AA];
__device__ float g_gateF[BB * ENC];
__device__ float g_initP[SP_INIT * BB * 1024];
__device__ float g_gatesP[SP_GT * BB * 4 * HH];

// pre-split bf16 hi/lo packed (2 bf16 per unsigned, K-pairs)
__device__ unsigned g_fcWh[VV * 256],  g_fcWl[VV * 256];     // fc_W   [32000][512]
__device__ unsigned g_gWh[2048 * 1536], g_gWl[2048 * 1536];  // [Wih|Whh] [2048][3072]
__device__ unsigned g_hWh[2560 * 256], g_hWl[2560 * 256];    // [h2aW;fbW] [2560][512]
__device__ unsigned g_e2h[512 * 1024], g_e2l[512 * 1024];    // e2aW [512][2048]
__device__ unsigned g_hbh[BB * 256],  g_hbl[BB * 256];       // h split
__device__ unsigned g_cxh[BB * 1024], g_cxl[BB * 1024];      // ctx split

__device__ __forceinline__ float sigmf(float x) { return 1.0f / (1.0f + expf(-x)); }

#define LD4(p)  (*(const float4*)&(p))
#define LDU4(p) (*(const uint4*)&(p))

__device__ __forceinline__ void split2(float x0, float x1, unsigned& hi, unsigned& lo) {
    __nv_bfloat16 h0 = __float2bfloat16_rn(x0);
    __nv_bfloat16 h1 = __float2bfloat16_rn(x1);
    __nv_bfloat16 l0 = __float2bfloat16_rn(x0 - __bfloat162float(h0));
    __nv_bfloat16 l1 = __float2bfloat16_rn(x1 - __bfloat162float(h1));
    hi = ((unsigned)__bfloat16_as_ushort(h1) << 16) | __bfloat16_as_ushort(h0);
    lo = ((unsigned)__bfloat16_as_ushort(l1) << 16) | __bfloat16_as_ushort(l0);
}

__device__ __forceinline__ void mma_bf16(float c[4], unsigned a0, unsigned a1,
                                         unsigned a2, unsigned a3,
                                         unsigned b0, unsigned b1) {
    asm volatile(
        "mma.sync.aligned.m16n8k16.row.col.f32.bf16.bf16.f32 "
        "{%0,%1,%2,%3},{%4,%5,%6,%7},{%8,%9},{%0,%1,%2,%3};"
        : "+f"(c[0]), "+f"(c[1]), "+f"(c[2]), "+f"(c[3])
        : "r"(a0), "r"(a1), "r"(a2), "r"(a3), "r"(b0), "r"(b1));
}

// ---------------- MMA pipeline: 64x128 tile, K chunks of 32, ping-pong 1-sync ----------------
// AFETCH: uses kc2 (u32 chunk base), fills rAu,rAv (uint4 hi/lo for 8 K-pairs of row ar)
// BFETCH: uses kc2, fills rBu0,rBu1,rBv0,rBv1 for row n0+br
#define MMA_PIPE(AFETCH, BFETCH, KC2START, NCHUNKS, TMASK)                      \
    extern __shared__ unsigned smem_u[];                                        \
    int tid = threadIdx.x;                                                      \
    int n0 = blockIdx.x * 128;                                                  \
    int warp = tid >> 5, lane = tid & 31;                                       \
    int mw = warp >> 1, nh = warp & 1;                                          \
    int g = lane >> 2, tig = lane & 3;                                          \
    int ar = tid >> 2, aq = tid & 3;                                            \
    int br = tid >> 1, bq = tid & 1;                                            \
    int myact = (g_dlen[mw * 16] > (TMASK));                                    \
    float c[8][4];                                                              \
    _Pragma("unroll")                                                           \
    for (int i = 0; i < 8; ++i) c[i][0] = c[i][1] = c[i][2] = c[i][3] = 0.f;    \
    uint4 rAu, rAv, rBu0, rBu1, rBv0, rBv1;                                     \
    { int kc2 = (KC2START); AFETCH; BFETCH; }                                   \
    for (int ch = 0; ch < (NCHUNKS); ++ch) {                                    \
        unsigned* sb = smem_u + (ch & 1) * SM_BUF;                              \
        { int aoff = ar * 17 + aq * 4;                                          \
          sb[aoff+0]=rAu.x; sb[aoff+1]=rAu.y; sb[aoff+2]=rAu.z; sb[aoff+3]=rAu.w; \
          sb[SM_AL+aoff+0]=rAv.x; sb[SM_AL+aoff+1]=rAv.y;                       \
          sb[SM_AL+aoff+2]=rAv.z; sb[SM_AL+aoff+3]=rAv.w;                       \
          int boff = SM_BH + br * 17 + bq * 8;                                  \
          sb[boff+0]=rBu0.x; sb[boff+1]=rBu0.y; sb[boff+2]=rBu0.z; sb[boff+3]=rBu0.w; \
          sb[boff+4]=rBu1.x; sb[boff+5]=rBu1.y; sb[boff+6]=rBu1.z; sb[boff+7]=rBu1.w; \
          int loff = boff + (SM_BL - SM_BH);                                    \
          sb[loff+0]=rBv0.x; sb[loff+1]=rBv0.y; sb[loff+2]=rBv0.z; sb[loff+3]=rBv0.w; \
          sb[loff+4]=rBv1.x; sb[loff+5]=rBv1.y; sb[loff+6]=rBv1.z; sb[loff+7]=rBv1.w; } \
        __syncthreads();                                                        \
        if (ch + 1 < (NCHUNKS)) { int kc2 = (KC2START) + (ch + 1) * 16; AFETCH; BFETCH; } \
        if (myact) {                                                            \
            _Pragma("unroll")                                                   \
            for (int ks = 0; ks < 2; ++ks) {                                    \
                int kb = ks * 8;                                                \
                int r0 = mw * 16 + g, r1 = r0 + 8;                              \
                unsigned a0 = sb[r0*17+kb+tig],   a1 = sb[r1*17+kb+tig];        \
                unsigned a2 = sb[r0*17+kb+4+tig], a3 = sb[r1*17+kb+4+tig];      \
                unsigned l0 = sb[SM_AL+r0*17+kb+tig],   l1 = sb[SM_AL+r1*17+kb+tig]; \
                unsigned l2 = sb[SM_AL+r0*17+kb+4+tig], l3 = sb[SM_AL+r1*17+kb+4+tig]; \
                _Pragma("unroll")                                               \
                for (int nt = 0; nt < 8; ++nt) {                                \
                    int colr = nh * 64 + nt * 8 + g;                            \
                    unsigned b0 = sb[SM_BH+colr*17+kb+tig];                     \
                    unsigned b1 = sb[SM_BH+colr*17+kb+4+tig];                   \
                    unsigned lb0 = sb[SM_BL+colr*17+kb+tig];                    \
                    unsigned lb1 = sb[SM_BL+colr*17+kb+4+tig];                  \
                    mma_bf16(c[nt], a0, a1, a2, a3, b0, b1);                    \
                    mma_bf16(c[nt], l0, l1, l2, l3, b0, b1);                    \
                    mma_bf16(c[nt], a0, a1, a2, a3, lb0, lb1);                  \
                }                                                               \
            }                                                                   \
        }                                                                       \
    }

#define BFETCH_PRE(BH, BL, RS)                                                  \
    { int k2b = kc2 + bq * 8;                                                   \
      const unsigned* ph = (BH) + (size_t)(n0 + br) * (RS) + k2b;               \
      const unsigned* pl = (BL) + (size_t)(n0 + br) * (RS) + k2b;               \
      rBu0 = LDU4(ph[0]); rBu1 = LDU4(ph[4]);                                   \
      rBv0 = LDU4(pl[0]); rBv1 = LDU4(pl[4]); }

#define AFETCH_H                                                                \
    { int k2a = kc2 + aq * 4;                                                   \
      rAu = LDU4(g_hbh[ar * 256 + k2a]);                                        \
      rAv = LDU4(g_hbl[ar * 256 + k2a]); }

// ---------------- FFMA GEMM body (init only) ----------------
#define GEMM2_BODY(AFETCH4, WFETCH4, KSTART, KTILES)                            \
    __shared__ float As[2][TK][TM + 4];                                         \
    __shared__ float Ws[2][TK][TN + 4];                                         \
    int tid = threadIdx.x;                                                      \
    int tx = tid & 31, ty = tid >> 5;                                           \
    int n0 = blockIdx.x * TN;                                                   \
    int arow = tid >> 2, kq = tid & 3;                                          \
    int brow0 = tid >> 2, brow1 = (tid >> 2) + 64;                              \
    float acc[8][4] = {};                                                       \
    float4 rA, rB0, rB1;                                                        \
    {                                                                           \
        int k = (KSTART) + kq * 4;                                              \
        rA = AFETCH4(arow, k);                                                  \
        rB0 = WFETCH4(brow0, k);                                                \
        rB1 = WFETCH4(brow1, k);                                                \
    }                                                                           \
    As[0][kq * 4 + 0][arow] = rA.x;  As[0][kq * 4 + 1][arow] = rA.y;            \
    As[0][kq * 4 + 2][arow] = rA.z;  As[0][kq * 4 + 3][arow] = rA.w;            \
    Ws[0][kq * 4 + 0][brow0] = rB0.x; Ws[0][kq * 4 + 1][brow0] = rB0.y;         \
    Ws[0][kq * 4 + 2][brow0] = rB0.z; Ws[0][kq * 4 + 3][brow0] = rB0.w;         \
    Ws[0][kq * 4 + 0][brow1] = rB1.x; Ws[0][kq * 4 + 1][brow1] = rB1.y;         \
    Ws[0][kq * 4 + 2][brow1] = rB1.z; Ws[0][kq * 4 + 3][brow1] = rB1.w;         \
    __syncthreads();                                                            \
    for (int tile = 0; tile < (KTILES); ++tile) {                               \
        int buf = tile & 1;                                                     \
        bool more = (tile + 1) < (KTILES);                                      \
        if (more) {                                                             \
            int k = (KSTART) + (tile + 1) * TK + kq * 4;                        \
            rA = AFETCH4(arow, k);                                              \
            rB0 = WFETCH4(brow0, k);                                            \
            rB1 = WFETCH4(brow1, k);                                            \
        }                                                                       \
        _Pragma("unroll")                                                       \
        for (int kk = 0; kk < TK; ++kk) {                                       \
            float4 a0 = *(const float4*)&As[buf][kk][ty * 8];                   \
            float4 a1 = *(const float4*)&As[buf][kk][ty * 8 + 4];               \
            float4 wv = *(const float4*)&Ws[buf][kk][tx * 4];                   \
            float av[8] = {a0.x, a0.y, a0.z, a0.w, a1.x, a1.y, a1.z, a1.w};     \
            float wr[4] = {wv.x, wv.y, wv.z, wv.w};                             \
            _Pragma("unroll")                                                   \
            for (int i = 0; i < 8; ++i)                                         \
                _Pragma("unroll")                                               \
                for (int j = 0; j < 4; ++j) acc[i][j] += av[i] * wr[j];         \
        }                                                                       \
        __syncthreads();                                                        \
        if (more) {                                                             \
            int nb = buf ^ 1;                                                   \
            As[nb][kq * 4 + 0][arow] = rA.x;  As[nb][kq * 4 + 1][arow] = rA.y;  \
            As[nb][kq * 4 + 2][arow] = rA.z;  As[nb][kq * 4 + 3][arow] = rA.w;  \
            Ws[nb][kq * 4 + 0][brow0] = rB0.x; Ws[nb][kq * 4 + 1][brow0] = rB0.y;\
            Ws[nb][kq * 4 + 2][brow0] = rB0.z; Ws[nb][kq * 4 + 3][brow0] = rB0.w;\
            Ws[nb][kq * 4 + 0][brow1] = rB1.x; Ws[nb][kq * 4 + 1][brow1] = rB1.y;\
            Ws[nb][kq * 4 + 2][brow1] = rB1.z; Ws[nb][kq * 4 + 3][brow1] = rB1.w;\
            __syncthreads();                                                    \
        }                                                                       \
    }

// ---------------- weight split kernels ----------------
__global__ void k_split(const float* __restrict__ s, unsigned* __restrict__ dh,
                        unsigned* __restrict__ dl, int n2) {
    int i = blockIdx.x * 256 + threadIdx.x;
    if (i < n2) {
        float2 v = *(const float2*)&s[2 * (size_t)i];
        unsigned h, l; split2(v.x, v.y, h, l);
        dh[i] = h; dl[i] = l;
    }
}
__global__ void k_split_cat(const float* __restrict__ Asrc, int ka,
                            const float* __restrict__ Bsrc, int kb,
                            unsigned* __restrict__ dh, unsigned* __restrict__ dl,
                            int rows) {
    int K2 = (ka + kb) >> 1;
    int i = blockIdx.x * 256 + threadIdx.x;
    if (i < rows * K2) {
        int r = i / K2, k = (i % K2) * 2;
        float x0, x1;
        if (k < ka) { x0 = Asrc[(size_t)r * ka + k]; x1 = Asrc[(size_t)r * ka + k + 1]; }
        else { x0 = Bsrc[(size_t)r * kb + k - ka]; x1 = Bsrc[(size_t)r * kb + k - ka + 1]; }
        unsigned h, l; split2(x0, x1, h, l);
        dh[i] = h; dl[i] = l;
    }
}

// ---------------- sort / layout detect ----------------
__global__ void k_sort(const int* __restrict__ y32, float* __restrict__ out, size_t cap) {
    __shared__ int len[BB];
    __shared__ int stride_s;
    int i = threadIdx.x;
    if (i == 0) {
        int odd = 0;
        for (int l = 0; l < LL; ++l) odd |= (y32[2 * l + 1] != 0);
        stride_s = odd ? 1 : 2;
        g_ystride = stride_s;
    }
    __syncthreads();
    int stride = stride_s;
    if (i < BB) {
        int c = 0;
        for (int l = 0; l < LL; ++l) c += (y32[(i * LL + l) * stride] != 0);
        len[i] = c;
    }
    __syncthreads();
    if (i < BB) {
        int r = 0;
        for (int j = 0; j < BB; ++j)
            r += (len[j] > len[i]) || (len[j] == len[i] && j < i);
        g_sidx[r] = i;
        g_dlen[r] = len[i] - 1;
        size_t base = PRED_SZ + ALPHA_SZ;
        if (base + r < cap)      out[base + r]      = (float)(len[i] - 1);
        if (base + BB + r < cap) out[base + BB + r] = (float)i;
    }
}

// ---------------- mean over P ----------------
__global__ void k_mean(const float* __restrict__ enc) {
    int b = blockIdx.x;
    int e = blockIdx.y * 256 + threadIdx.x;
    const float* base = enc + (size_t)g_sidx[b] * PP * ENC + e;
    float s = 0.f;
    #pragma unroll 8
    for (int p = 0; p < PP; ++p) s += base[p * ENC];
    g_mean[b * ENC + e] = s * (1.0f / PP);
}

// ---------------- init h0/c0 GEMM + reduce ----------------
__global__ __launch_bounds__(256) void k_init_gemm(const float* __restrict__ ihW,
                                                   const float* __restrict__ icW) {
    int z = blockIdx.z;
#define A_INIT(row, k) LD4(g_mean[(row) * ENC + (k)])
#define W_INIT(row, k) ((n0 + (row)) < HH ? LD4(ihW[(n0 + (row)) * ENC + (k)]) \
                                          : LD4(icW[(n0 + (row) - HH) * ENC + (k)]))
    GEMM2_BODY(A_INIT, W_INIT, z * (ENC / SP_INIT), (ENC / SP_INIT) / TK);
    float* P = g_initP + (size_t)z * BB * 1024;
    #pragma unroll
    for (int i = 0; i < 8; ++i) {
        int m = ty * 8 + i;
        *(float4*)&P[m * 1024 + n0 + tx * 4] =
            make_float4(acc[i][0], acc[i][1], acc[i][2], acc[i][3]);
    }
#undef A_INIT
#undef W_INIT
}

__global__ void k_init_red(const float* __restrict__ ihb, const float* __restrict__ icb) {
    int b = blockIdx.x, t2 = threadIdx.x;   // 256 threads
    float hv[2];
    #pragma unroll
    for (int q = 0; q < 2; ++q) {
        int n = 2 * t2 + q;
        float sh = ihb[n], sc = icb[n];
        #pragma unroll
        for (int z = 0; z < SP_INIT; ++z) {
            const float* P = g_initP + ((size_t)z * BB + b) * 1024;
            sh += P[n];
            sc += P[512 + n];
        }
        g_h[b * HH + n] = sh;
        g_c[b * HH + n] = sc;
        hv[q] = sh;
    }
    unsigned hh, ll; split2(hv[0], hv[1], hh, ll);
    g_hbh[b * 256 + t2] = hh;
    g_hbl[b * 256 + t2] = ll;
}

// ---------------- att1 (MMA): enc_sorted @ e2aW^T ----------------
__global__ __launch_bounds__(256) void k_att1_mma(const float* __restrict__ enc) {
    __shared__ int rowOff[64];
    int m0 = blockIdx.y * 64;
    if (threadIdx.x < 64) {
        int m = m0 + threadIdx.x;
        int b = m / PP, p = m % PP;
        rowOff[threadIdx.x] = (g_sidx[b] * PP + p) * ENC;
    }
    __syncthreads();
#define AFETCH_ENC                                                              \
    { int ka = 2 * kc2 + aq * 8;                                                \
      const float* pe = enc + rowOff[ar] + ka;                                  \
      float4 f0 = LD4(pe[0]), f1 = LD4(pe[4]);                                  \
      split2(f0.x, f0.y, rAu.x, rAv.x); split2(f0.z, f0.w, rAu.y, rAv.y);       \
      split2(f1.x, f1.y, rAu.z, rAv.z); split2(f1.z, f1.w, rAu.w, rAv.w); }
    MMA_PIPE(AFETCH_ENC, BFETCH_PRE(g_e2h, g_e2l, 1024), 0, ENC / 32, -1);
    #pragma unroll
    for (int nt = 0; nt < 8; ++nt) {
        int col = n0 + nh * 64 + nt * 8 + 2 * tig;
        int r0 = mw * 16 + g, r1 = r0 + 8;
        g_att1[(size_t)(m0 + r0) * AA + col]     = c[nt][0];
        g_att1[(size_t)(m0 + r0) * AA + col + 1] = c[nt][1];
        g_att1[(size_t)(m0 + r1) * AA + col]     = c[nt][2];
        g_att1[(size_t)(m0 + r1) * AA + col + 1] = c[nt][3];
    }
#undef AFETCH_ENC
}

// ---------------- hW (MMA): h @ [h2aW;fbW]^T -> att2F + gateF(sigmoid) ----------------
__global__ __launch_bounds__(256) void k_hw(const float* __restrict__ fbb, int t) {
    MMA_PIPE(AFETCH_H, BFETCH_PRE(g_hWh, g_hWl, 256), 0, HH / 32, t);
    #pragma unroll
    for (int nt = 0; nt < 8; ++nt) {
        int col = n0 + nh * 64 + nt * 8 + 2 * tig;
        int r0 = mw * 16 + g, r1 = r0 + 8;
        float v[4] = {c[nt][0], c[nt][1], c[nt][2], c[nt][3]};
        int rr[4] = {r0, r0, r1, r1};
        int cc[4] = {col, col + 1, col, col + 1};
        #pragma unroll
        for (int q = 0; q < 4; ++q) {
            if (cc[q] < AA) g_att2F[rr[q] * AA + cc[q]] = v[q];
            else {
                int e = cc[q] - AA;
                g_gateF[rr[q] * ENC + e] = sigmf(v[q] + fbb[e]);
            }
        }
    }
}

// ---------------- score + softmax + alpha ----------------
__global__ __launch_bounds__(512) void k_score(const float* __restrict__ attW,
                                               const float* __restrict__ attb,
                                               float* __restrict__ out, size_t cap, int t) {
    __shared__ float a2[AA];
    __shared__ float aw[AA];
    __shared__ float sc[PP];
    __shared__ float red[2];
    int b = blockIdx.x, tid = threadIdx.x;
    if (g_dlen[b] <= t) {
        for (int p = tid; p < PP; p += 512) {
            size_t idx = PRED_SZ + (size_t)(b * TT + t) * PP + p;
            if (idx < cap) out[idx] = 0.f;
        }
        return;
    }
    for (int i = tid; i < AA; i += 512) {
        a2[i] = g_att2F[b * AA + i];
        aw[i] = attW[i];
    }
    __syncthreads();
    int w = tid >> 5, lane = tid & 31;
    for (int p = w; p < PP; p += 16) {
        const float* base = g_att1 + (size_t)(b * PP + p) * AA;
        float s = 0.f;
        #pragma unroll 4
        for (int a0 = lane; a0 < AA; a0 += 32) {
            float v = base[a0] + a2[a0];
            s += fmaxf(v, 0.f) * aw[a0];
        }
        #pragma unroll
        for (int o = 16; o; o >>= 1) s += __shfl_down_sync(0xFFFFFFFFu, s, o);
        if (lane == 0) sc[p] = s + attb[0];
    }
    __syncthreads();
    if (w == 0) {
        float mx = -1e30f;
        for (int p = lane; p < PP; p += 32) mx = fmaxf(mx, sc[p]);
        #pragma unroll
        for (int o = 16; o; o >>= 1) mx = fmaxf(mx, __shfl_xor_sync(0xFFFFFFFFu, mx, o));
        float sm = 0.f;
        for (int p = lane; p < PP; p += 32) sm += expf(sc[p] - mx);
        #pragma unroll
        for (int o = 16; o; o >>= 1) sm += __shfl_xor_sync(0xFFFFFFFFu, sm, o);
        if (lane == 0) { red[0] = mx; red[1] = 1.0f / sm; }
    }
    __syncthreads();
    float mx = red[0], inv = red[1];
    for (int p = tid; p < PP; p += 512) {
        float al = expf(sc[p] - mx) * inv;
        g_alpha[b * PP + p] = al;
        size_t idx = PRED_SZ + (size_t)(b * TT + t) * PP + p;
        if (idx < cap) out[idx] = al;
    }
}

// ---------------- ctx: gate * (alpha @ enc), emits packed bf split ----------------
__global__ void k_ctx(const float* __restrict__ enc, int t) {
    __shared__ float al[PP];
    int b = blockIdx.x;
    if (g_dlen[b] <= t) return;
    int tid = threadIdx.x;               // 256
    int e0 = blockIdx.y * 512 + 2 * tid;
    if (tid < PP) al[tid] = g_alpha[b * PP + tid];
    __syncthreads();
    const float* base = enc + (size_t)g_sidx[b] * PP * ENC + e0;
    float s0 = 0.f, s1 = 0.f;
    #pragma unroll 4
    for (int p = 0; p < PP; ++p) {
        float2 v = *(const float2*)&base[p * ENC];
        s0 += al[p] * v.x;
        s1 += al[p] * v.y;
    }
    float2 gt = *(const float2*)&g_gateF[b * ENC + e0];
    unsigned h, l; split2(gt.x * s0, gt.y * s1, h, l);
    int k2 = e0 >> 1;
    g_cxh[b * 1024 + k2] = h;
    g_cxl[b * 1024 + k2] = l;
}

// ---------------- gates (MMA): [emb|ctx|h] @ gW^T, K-split x8 ----------------
__global__ __launch_bounds__(256) void k_gates_mma(const int* __restrict__ y32,
                                                   const float* __restrict__ emb, int t) {
    __shared__ int tokOffF[64];
    if (threadIdx.x < 64) {
        int tok = y32[(g_sidx[threadIdx.x] * LL + t) * g_ystride];
        tok = max(0, min(tok, VV - 1));
        tokOffF[threadIdx.x] = tok * EE;
    }
    __syncthreads();
    int z = blockIdx.z;
#define AFETCH_GT                                                               \
    { int k2a = kc2 + aq * 4;                                                   \
      if (k2a < 256) {                                                          \
          const float* pe = emb + tokOffF[ar] + 2 * k2a;                        \
          float4 f0 = LD4(pe[0]), f1 = LD4(pe[4]);                              \
          split2(f0.x, f0.y, rAu.x, rAv.x); split2(f0.z, f0.w, rAu.y, rAv.y);   \
          split2(f1.x, f1.y, rAu.z, rAv.z); split2(f1.z, f1.w, rAu.w, rAv.w);   \
      } else if (k2a < 1280) {                                                  \
          rAu = LDU4(g_cxh[ar * 1024 + k2a - 256]);                             \
          rAv = LDU4(g_cxl[ar * 1024 + k2a - 256]);                             \
      } else {                                                                  \
          rAu = LDU4(g_hbh[ar * 256 + k2a - 1280]);                             \
          rAv = LDU4(g_hbl[ar * 256 + k2a - 1280]);                             \
      } }
    MMA_PIPE(AFETCH_GT, BFETCH_PRE(g_gWh, g_gWl, 1536), z * 192, 12, t);
    float* P = g_gatesP + (size_t)z * BB * 4 * HH;
    #pragma unroll
    for (int nt = 0; nt < 8; ++nt) {
        int col = n0 + nh * 64 + nt * 8 + 2 * tig;
        int r0 = mw * 16 + g, r1 = r0 + 8;
        P[r0 * (4 * HH) + col]     = c[nt][0];
        P[r0 * (4 * HH) + col + 1] = c[nt][1];
        P[r1 * (4 * HH) + col]     = c[nt][2];
        P[r1 * (4 * HH) + col + 1] = c[nt][3];
    }
#undef AFETCH_GT
}

// ---------------- LSTM: reduce partials, update h/c, emit h split ----------------
__global__ void k_lstm(const float* __restrict__ bih, const float* __restrict__ bhh, int t) {
    int b = blockIdx.x, t2 = threadIdx.x;   // 256 threads
    if (g_dlen[b] <= t) return;
    float hv[2];
    #pragma unroll
    for (int q = 0; q < 2; ++q) {
        int j = 2 * t2 + q;
        float gs[4];
        #pragma unroll
        for (int gI = 0; gI < 4; ++gI) {
            int n = gI * HH + j;
            float s = bih[n] + bhh[n];
            #pragma unroll
            for (int z = 0; z < SP_GT; ++z)
                s += g_gatesP[((size_t)z * BB + b) * (4 * HH) + n];
            gs[gI] = s;
        }
        float ig = sigmf(gs[0]);
        float fg = sigmf(gs[1]);
        float gg = tanhf(gs[2]);
        float og = sigmf(gs[3]);
        float cv = fg * g_c[b * HH + j] + ig * gg;
        g_c[b * HH + j] = cv;
        float h = og * tanhf(cv);
        g_h[b * HH + j] = h;
        hv[q] = h;
    }
    unsigned hh, ll; split2(hv[0], hv[1], hh, ll);
    g_hbh[b * 256 + t2] = hh;
    g_hbl[b * 256 + t2] = ll;
}

// ---------------- logits (MMA) + masked bounded write ----------------
__global__ __launch_bounds__(256) void k_logits_mma(const float* __restrict__ fcb,
                                                    float* __restrict__ out, size_t cap, int t) {
    MMA_PIPE(AFETCH_H, BFETCH_PRE(g_fcWh, g_fcWl, 256), 0, HH / 32, t);
    #pragma unroll
    for (int nt = 0; nt < 8; ++nt) {
        int col = n0 + nh * 64 + nt * 8 + 2 * tig;
        int r0 = mw * 16 + g, r1 = r0 + 8;
        bool act0 = g_dlen[r0] > t, act1 = g_dlen[r1] > t;
        size_t i00 = ((size_t)r0 * TT + t) * VV + col;
        size_t i10 = ((size_t)r1 * TT + t) * VV + col;
        if (i00 + 1 < cap) {
            out[i00]     = act0 ? c[nt][0] + fcb[col]     : 0.f;
            out[i00 + 1] = act0 ? c[nt][1] + fcb[col + 1] : 0.f;
        }
        if (i10 + 1 < cap) {
            out[i10]     = act1 ? c[nt][2] + fcb[col]     : 0.f;
            out[i10 + 1] = act1 ? c[nt][3] + fcb[col + 1] : 0.f;
        }
    }
}

// ---------------- launch ----------------
extern "C" void kernel_launch(void* const* d_in, const int* in_sizes, int n_in,
                              void* d_out, int out_size) {
    if (n_in < 19) return;
    const float* enc  = (const float*)d_in[0];
    const int*   y32  = (const int*)d_in[1];
    const float* emb  = (const float*)d_in[2];
    const float* e2aW = (const float*)d_in[3];
    const float* h2aW = (const float*)d_in[4];
    const float* attW = (const float*)d_in[5];
    const float* attb = (const float*)d_in[6];
    const float* fbW  = (const float*)d_in[7];
    const float* fbb  = (const float*)d_in[8];
    const float* Wih  = (const float*)d_in[9];
    const float* bih  = (const float*)d_in[10];
    const float* Whh  = (const float*)d_in[11];
    const float* bhh  = (const float*)d_in[12];
    const float* fcW  = (const float*)d_in[13];
    const float* fcb  = (const float*)d_in[14];
    const float* ihW  = (const float*)d_in[15];
    const float* ihb  = (const float*)d_in[16];
    const float* icW  = (const float*)d_in[17];
    const float* icb  = (const float*)d_in[18];

    float* out = (float*)d_out;
    size_t cap = (size_t)out_size;

    static int attr_done = 0;
    if (!attr_done) {
        cudaFuncSetAttribute(k_att1_mma,   cudaFuncAttributeMaxDynamicSharedMemorySize, SM_BYTES);
        cudaFuncSetAttribute(k_hw,         cudaFuncAttributeMaxDynamicSharedMemorySize, SM_BYTES);
        cudaFuncSetAttribute(k_gates_mma,  cudaFuncAttributeMaxDynamicSharedMemorySize, SM_BYTES);
        cudaFuncSetAttribute(k_logits_mma, cudaFuncAttributeMaxDynamicSharedMemorySize, SM_BYTES);
        attr_done = 1;
    }

    unsigned *p_fcWh, *p_fcWl, *p_e2h, *p_e2l, *p_gWh, *p_gWl, *p_hWh, *p_hWl;
    cudaGetSymbolAddress((void**)&p_fcWh, g_fcWh);
    cudaGetSymbolAddress((void**)&p_fcWl, g_fcWl);
    cudaGetSymbolAddress((void**)&p_e2h,  g_e2h);
    cudaGetSymbolAddress((void**)&p_e2l,  g_e2l);
    cudaGetSymbolAddress((void**)&p_gWh,  g_gWh);
    cudaGetSymbolAddress((void**)&p_gWl,  g_gWl);
    cudaGetSymbolAddress((void**)&p_hWh,  g_hWh);
    cudaGetSymbolAddress((void**)&p_hWl,  g_hWl);

    // preamble
    k_sort<<<1, 64>>>(y32, out, cap);
    k_mean<<<dim3(BB, ENC / 256), 256>>>(enc);
    k_init_gemm<<<dim3(1024 / TN, 1, SP_INIT), 256>>>(ihW, icW);
    k_init_red<<<BB, 256>>>(ihb, icb);

    // weight splits (once per launch; emb NOT pre-split)
    k_split<<<(VV * 256 + 255) / 256, 256>>>(fcW, p_fcWh, p_fcWl, VV * 256);
    k_split<<<(512 * 1024 + 255) / 256, 256>>>(e2aW, p_e2h, p_e2l, 512 * 1024);
    k_split_cat<<<(2048 * 1536 + 255) / 256, 256>>>(Wih, EE + ENC, Whh, HH,
                                                    p_gWh, p_gWl, 2048);
    k_split<<<(512 * 256 + 255) / 256, 256>>>(h2aW, p_hWh, p_hWl, 512 * 256);
    k_split<<<(2048 * 256 + 255) / 256, 256>>>(fbW, p_hWh + 512 * 256,
                                               p_hWl + 512 * 256, 2048 * 256);

    k_att1_mma<<<dim3(AA / 128, (BB * PP) / 64), 256, SM_BYTES>>>(enc);

    for (int t = 0; t < TT; ++t) {
        k_hw<<<2560 / 128, 256, SM_BYTES>>>(fbb, t);
        k_score<<<BB, 512>>>(attW, attb, out, cap, t);
        k_ctx<<<dim3(BB, 4), 256>>>(enc, t);
        k_gates_mma<<<dim3((4 * HH) / 128, 1, SP_GT), 256, SM_BYTES>>>(y32, emb, t);
        k_lstm<<<BB, 256>>>(bih, bhh, t);
        k_logits_mma<<<VV / 128, 256, SM_BYTES>>>(fcb, out, cap, t);
    }
}

// round 13
// speedup vs baseline: 1.0867x; 1.0446x over previous
#include <cuda_runtime.h>
#include <cuda_bf16.h>

// Problem dims (fixed)
#define BB 64
#define PP 196
#define ENC 2048
#define LL 20
#define TT 19
#define VV 32000
#define HH 512
#define EE 512
#define AA 512

#define PRED_SZ ((size_t)BB * TT * VV)
#define ALPHA_SZ ((size_t)BB * TT * PP)

// FFMA GEMM tile config (init kernel)
#define TM 64
#define TN 128
#define TK 16
#define SP_INIT 8
#define SP_GT   8

// smem layout for MMA pipe (u32 words): per buffer 6528 = Ah(1088)+Al(1088)+Bh(2176)+Bl(2176)
#define SM_BUF   6528
#define SM_AL    1088
#define SM_BH    2176
#define SM_BL    4352
#define SM_BYTES (2 * SM_BUF * 4)

// ---------------- scratch (device globals; no allocation) ----------------
__device__ int   g_sidx[BB];
__device__ int   g_dlen[BB];
__device__ int   g_ystride;
__device__ float g_mean[BB * ENC];
__device__ float g_h[BB * HH];
__device__ float g_c[BB * HH];
__device__ float g_att1[BB * PP * AA];            // 25.7 MB
__device__ float g_alpha[BB * PP];
__device__ float g_att2F[BB * AA];
__device__ float g_gateF[BB * ENC];
__device__ float g_ctx[BB * ENC];
__device__ float g_initP[SP_INIT * BB * 1024];
__device__ float g_gatesP[SP_GT * BB * 4 * HH];

__device__ __forceinline__ float sigmf(float x) { return 1.0f / (1.0f + expf(-x)); }

#define LD4(p)  (*(const float4*)&(p))

// ---------------- fast truncation bf16 split (hi = trunc, lo = trunc(residual)) ----------------
__device__ __forceinline__ void fsplit2(float x0, float x1, unsigned& hi, unsigned& lo) {
    unsigned u0 = __float_as_uint(x0), u1 = __float_as_uint(x1);
    hi = __byte_perm(u0, u1, 0x7632);
    float l0 = x0 - __uint_as_float(u0 & 0xFFFF0000u);   // exact residual
    float l1 = x1 - __uint_as_float(u1 & 0xFFFF0000u);
    lo = __byte_perm(__float_as_uint(l0), __float_as_uint(l1), 0x7632);
}

__device__ __forceinline__ void mma_bf16(float c[4], unsigned a0, unsigned a1,
                                         unsigned a2, unsigned a3,
                                         unsigned b0, unsigned b1) {
    asm volatile(
        "mma.sync.aligned.m16n8k16.row.col.f32.bf16.bf16.f32 "
        "{%0,%1,%2,%3},{%4,%5,%6,%7},{%8,%9},{%0,%1,%2,%3};"
        : "+f"(c[0]), "+f"(c[1]), "+f"(c[2]), "+f"(c[3])
        : "r"(a0), "r"(a1), "r"(a2), "r"(a3), "r"(b0), "r"(b1));
}

// ---------------- MMA pipeline: 64x128 tile, K chunks of 32, ping-pong 1-sync ----------------
// AFETCH: uses kc2 (u32 chunk base), fills rAu,rAv (hi/lo for 8 K-pairs of row ar)
// BFETCH: uses kc2, fills rBu0,rBu1,rBv0,rBv1 for row n0+br (16 floats -> 8 pairs)
#define MMA_PIPE(AFETCH, BFETCH, KC2START, NCHUNKS, TMASK)                      \
    extern __shared__ unsigned smem_u[];                                        \
    int tid = threadIdx.x;                                                      \
    int n0 = blockIdx.x * 128;                                                  \
    int warp = tid >> 5, lane = tid & 31;                                       \
    int mw = warp >> 1, nh = warp & 1;                                          \
    int g = lane >> 2, tig = lane & 3;                                          \
    int ar = tid >> 2, aq = tid & 3;                                            \
    int br = tid >> 1, bq = tid & 1;                                            \
    int myact = (g_dlen[mw * 16] > (TMASK));                                    \
    float c[8][4];                                                              \
    _Pragma("unroll")                                                           \
    for (int i = 0; i < 8; ++i) c[i][0] = c[i][1] = c[i][2] = c[i][3] = 0.f;    \
    uint4 rAu, rAv, rBu0, rBu1, rBv0, rBv1;                                     \
    { int kc2 = (KC2START); AFETCH; BFETCH; }                                   \
    for (int ch = 0; ch < (NCHUNKS); ++ch) {                                    \
        unsigned* sb = smem_u + (ch & 1) * SM_BUF;                              \
        { int aoff = ar * 17 + aq * 4;                                          \
          sb[aoff+0]=rAu.x; sb[aoff+1]=rAu.y; sb[aoff+2]=rAu.z; sb[aoff+3]=rAu.w; \
          sb[SM_AL+aoff+0]=rAv.x; sb[SM_AL+aoff+1]=rAv.y;                       \
          sb[SM_AL+aoff+2]=rAv.z; sb[SM_AL+aoff+3]=rAv.w;                       \
          int boff = SM_BH + br * 17 + bq * 8;                                  \
          sb[boff+0]=rBu0.x; sb[boff+1]=rBu0.y; sb[boff+2]=rBu0.z; sb[boff+3]=rBu0.w; \
          sb[boff+4]=rBu1.x; sb[boff+5]=rBu1.y; sb[boff+6]=rBu1.z; sb[boff+7]=rBu1.w; \
          int loff = boff + (SM_BL - SM_BH);                                    \
          sb[loff+0]=rBv0.x; sb[loff+1]=rBv0.y; sb[loff+2]=rBv0.z; sb[loff+3]=rBv0.w; \
          sb[loff+4]=rBv1.x; sb[loff+5]=rBv1.y; sb[loff+6]=rBv1.z; sb[loff+7]=rBv1.w; } \
        __syncthreads();                                                        \
        if (ch + 1 < (NCHUNKS)) { int kc2 = (KC2START) + (ch + 1) * 16; AFETCH; BFETCH; } \
        if (myact) {                                                            \
            _Pragma("unroll")                                                   \
            for (int ks = 0; ks < 2; ++ks) {                                    \
                int kb = ks * 8;                                                \
                int r0 = mw * 16 + g, r1 = r0 + 8;                              \
                unsigned a0 = sb[r0*17+kb+tig],   a1 = sb[r1*17+kb+tig];        \
                unsigned a2 = sb[r0*17+kb+4+tig], a3 = sb[r1*17+kb+4+tig];      \
                unsigned l0 = sb[SM_AL+r0*17+kb+tig],   l1 = sb[SM_AL+r1*17+kb+tig]; \
                unsigned l2 = sb[SM_AL+r0*17+kb+4+tig], l3 = sb[SM_AL+r1*17+kb+4+tig]; \
                _Pragma("unroll")                                               \
                for (int nt = 0; nt < 8; ++nt) {                                \
                    int colr = nh * 64 + nt * 8 + g;                            \
                    unsigned b0 = sb[SM_BH+colr*17+kb+tig];                     \
                    unsigned b1 = sb[SM_BH+colr*17+kb+4+tig];                   \
                    unsigned lb0 = sb[SM_BL+colr*17+kb+tig];                    \
                    unsigned lb1 = sb[SM_BL+colr*17+kb+4+tig];                  \
                    mma_bf16(c[nt], a0, a1, a2, a3, b0, b1);                    \
                    mma_bf16(c[nt], l0, l1, l2, l3, b0, b1);                    \
                    mma_bf16(c[nt], a0, a1, a2, a3, lb0, lb1);                  \
                }                                                               \
            }                                                                   \
        }                                                                       \
    }

// B fetch from fp32 source: PTRK yields const float* already offset to this thread's 16 floats
#define BFETCH_FLT(PTRK)                                                        \
    { int kf = 2 * kc2 + bq * 16;                                               \
      const float* pb = (PTRK);                                                 \
      float4 q0 = LD4(pb[0]), q1 = LD4(pb[4]), q2 = LD4(pb[8]), q3 = LD4(pb[12]); \
      fsplit2(q0.x,q0.y,rBu0.x,rBv0.x); fsplit2(q0.z,q0.w,rBu0.y,rBv0.y);       \
      fsplit2(q1.x,q1.y,rBu0.z,rBv0.z); fsplit2(q1.z,q1.w,rBu0.w,rBv0.w);       \
      fsplit2(q2.x,q2.y,rBu1.x,rBv1.x); fsplit2(q2.z,q2.w,rBu1.y,rBv1.y);       \
      fsplit2(q3.x,q3.y,rBu1.z,rBv1.z); fsplit2(q3.z,q3.w,rBu1.w,rBv1.w); }

// A fetch from fp32 source: PTRK yields const float* offset to this thread's 8 floats
#define AFETCH_FLT(PTRK)                                                        \
    { int kf = 2 * kc2 + aq * 8;                                                \
      const float* pa = (PTRK);                                                 \
      float4 f0 = LD4(pa[0]), f1 = LD4(pa[4]);                                  \
      fsplit2(f0.x, f0.y, rAu.x, rAv.x); fsplit2(f0.z, f0.w, rAu.y, rAv.y);     \
      fsplit2(f1.x, f1.y, rAu.z, rAv.z); fsplit2(f1.z, f1.w, rAu.w, rAv.w); }

// ---------------- FFMA GEMM body (init only) ----------------
#define GEMM2_BODY(AFETCH4, WFETCH4, KSTART, KTILES)                            \
    __shared__ float As[2][TK][TM + 4];                                         \
    __shared__ float Ws[2][TK][TN + 4];                                         \
    int tid = threadIdx.x;                                                      \
    int tx = tid & 31, ty = tid >> 5;                                           \
    int n0 = blockIdx.x * TN;                                                   \
    int arow = tid >> 2, kq = tid & 3;                                          \
    int brow0 = tid >> 2, brow1 = (tid >> 2) + 64;                              \
    float acc[8][4] = {};                                                       \
    float4 rA, rB0, rB1;                                                        \
    {                                                                           \
        int k = (KSTART) + kq * 4;                                              \
        rA = AFETCH4(arow, k);                                                  \
        rB0 = WFETCH4(brow0, k);                                                \
        rB1 = WFETCH4(brow1, k);                                                \
    }                                                                           \
    As[0][kq * 4 + 0][arow] = rA.x;  As[0][kq * 4 + 1][arow] = rA.y;            \
    As[0][kq * 4 + 2][arow] = rA.z;  As[0][kq * 4 + 3][arow] = rA.w;            \
    Ws[0][kq * 4 + 0][brow0] = rB0.x; Ws[0][kq * 4 + 1][brow0] = rB0.y;         \
    Ws[0][kq * 4 + 2][brow0] = rB0.z; Ws[0][kq * 4 + 3][brow0] = rB0.w;         \
    Ws[0][kq * 4 + 0][brow1] = rB1.x; Ws[0][kq * 4 + 1][brow1] = rB1.y;         \
    Ws[0][kq * 4 + 2][brow1] = rB1.z; Ws[0][kq * 4 + 3][brow1] = rB1.w;         \
    __syncthreads();                                                            \
    for (int tile = 0; tile < (KTILES); ++tile) {                               \
        int buf = tile & 1;                                                     \
        bool more = (tile + 1) < (KTILES);                                      \
        if (more) {                                                             \
            int k = (KSTART) + (tile + 1) * TK + kq * 4;                        \
            rA = AFETCH4(arow, k);                                              \
            rB0 = WFETCH4(brow0, k);                                            \
            rB1 = WFETCH4(brow1, k);                                            \
        }                                                                       \
        _Pragma("unroll")                                                       \
        for (int kk = 0; kk < TK; ++kk) {                                       \
            float4 a0 = *(const float4*)&As[buf][kk][ty * 8];                   \
            float4 a1 = *(const float4*)&As[buf][kk][ty * 8 + 4];               \
            float4 wv = *(const float4*)&Ws[buf][kk][tx * 4];                   \
            float av[8] = {a0.x, a0.y, a0.z, a0.w, a1.x, a1.y, a1.z, a1.w};     \
            float wr[4] = {wv.x, wv.y, wv.z, wv.w};                             \
            _Pragma("unroll")                                                   \
            for (int i = 0; i < 8; ++i)                                         \
                _Pragma("unroll")                                               \
                for (int j = 0; j < 4; ++j) acc[i][j] += av[i] * wr[j];         \
        }                                                                       \
        __syncthreads();                                                        \
        if (more) {                                                             \
            int nb = buf ^ 1;                                                   \
            As[nb][kq * 4 + 0][arow] = rA.x;  As[nb][kq * 4 + 1][arow] = rA.y;  \
            As[nb][kq * 4 + 2][arow] = rA.z;  As[nb][kq * 4 + 3][arow] = rA.w;  \
            Ws[nb][kq * 4 + 0][brow0] = rB0.x; Ws[nb][kq * 4 + 1][brow0] = rB0.y;\
            Ws[nb][kq * 4 + 2][brow0] = rB0.z; Ws[nb][kq * 4 + 3][brow0] = rB0.w;\
            Ws[nb][kq * 4 + 0][brow1] = rB1.x; Ws[nb][kq * 4 + 1][brow1] = rB1.y;\
            Ws[nb][kq * 4 + 2][brow1] = rB1.z; Ws[nb][kq * 4 + 3][brow1] = rB1.w;\
            __syncthreads();                                                    \
        }                                                                       \
    }

// ---------------- sort / layout detect ----------------
__global__ void k_sort(const int* __restrict__ y32, float* __restrict__ out, size_t cap) {
    __shared__ int len[BB];
    __shared__ int stride_s;
    int i = threadIdx.x;
    if (i == 0) {
        int odd = 0;
        for (int l = 0; l < LL; ++l) odd |= (y32[2 * l + 1] != 0);
        stride_s = odd ? 1 : 2;
        g_ystride = stride_s;
    }
    __syncthreads();
    int stride = stride_s;
    if (i < BB) {
        int c = 0;
        for (int l = 0; l < LL; ++l) c += (y32[(i * LL + l) * stride] != 0);
        len[i] = c;
    }
    __syncthreads();
    if (i < BB) {
        int r = 0;
        for (int j = 0; j < BB; ++j)
            r += (len[j] > len[i]) || (len[j] == len[i] && j < i);
        g_sidx[r] = i;
        g_dlen[r] = len[i] - 1;
        size_t base = PRED_SZ + ALPHA_SZ;
        if (base + r < cap)      out[base + r]      = (float)(len[i] - 1);
        if (base + BB + r < cap) out[base + BB + r] = (float)i;
    }
}

// ---------------- mean over P ----------------
__global__ void k_mean(const float* __restrict__ enc) {
    int b = blockIdx.x;
    int e = blockIdx.y * 256 + threadIdx.x;
    const float* base = enc + (size_t)g_sidx[b] * PP * ENC + e;
    float s = 0.f;
    #pragma unroll 8
    for (int p = 0; p < PP; ++p) s += base[p * ENC];
    g_mean[b * ENC + e] = s * (1.0f / PP);
}

// ---------------- init h0/c0 GEMM + reduce ----------------
__global__ __launch_bounds__(256) void k_init_gemm(const float* __restrict__ ihW,
                                                   const float* __restrict__ icW) {
    int z = blockIdx.z;
#define A_INIT(row, k) LD4(g_mean[(row) * ENC + (k)])
#define W_INIT(row, k) ((n0 + (row)) < HH ? LD4(ihW[(n0 + (row)) * ENC + (k)]) \
                                          : LD4(icW[(n0 + (row) - HH) * ENC + (k)]))
    GEMM2_BODY(A_INIT, W_INIT, z * (ENC / SP_INIT), (ENC / SP_INIT) / TK);
    float* P = g_initP + (size_t)z * BB * 1024;
    #pragma unroll
    for (int i = 0; i < 8; ++i) {
        int m = ty * 8 + i;
        *(float4*)&P[m * 1024 + n0 + tx * 4] =
            make_float4(acc[i][0], acc[i][1], acc[i][2], acc[i][3]);
    }
#undef A_INIT
#undef W_INIT
}

__global__ void k_init_red(const float* __restrict__ ihb, const float* __restrict__ icb) {
    int b = blockIdx.x, n = threadIdx.x;    // 1024 threads
    float s = (n < HH) ? ihb[n] : icb[n - HH];
    #pragma unroll
    for (int z = 0; z < SP_INIT; ++z) s += g_initP[((size_t)z * BB + b) * 1024 + n];
    if (n < HH) g_h[b * HH + n] = s;
    else        g_c[b * HH + (n - HH)] = s;
}

// ---------------- att1 (MMA): enc_sorted @ e2aW^T ----------------
__global__ __launch_bounds__(256) void k_att1_mma(const float* __restrict__ enc,
                                                  const float* __restrict__ e2aW) {
    __shared__ int rowOff[64];
    int m0 = blockIdx.y * 64;
    if (threadIdx.x < 64) {
        int m = m0 + threadIdx.x;
        int b = m / PP, p = m % PP;
        rowOff[threadIdx.x] = (g_sidx[b] * PP + p) * ENC;
    }
    __syncthreads();
    MMA_PIPE(AFETCH_FLT(enc + rowOff[ar] + kf),
             BFETCH_FLT(e2aW + (size_t)(n0 + br) * ENC + kf),
             0, ENC / 32, -1);
    #pragma unroll
    for (int nt = 0; nt < 8; ++nt) {
        int col = n0 + nh * 64 + nt * 8 + 2 * tig;
        int r0 = mw * 16 + g, r1 = r0 + 8;
        g_att1[(size_t)(m0 + r0) * AA + col]     = c[nt][0];
        g_att1[(size_t)(m0 + r0) * AA + col + 1] = c[nt][1];
        g_att1[(size_t)(m0 + r1) * AA + col]     = c[nt][2];
        g_att1[(size_t)(m0 + r1) * AA + col + 1] = c[nt][3];
    }
}

// ---------------- hW (MMA): h @ [h2aW;fbW]^T -> att2F + gateF(sigmoid) ----------------
__global__ __launch_bounds__(256) void k_hw(const float* __restrict__ h2aW,
                                            const float* __restrict__ fbW,
                                            const float* __restrict__ fbb, int t) {
    MMA_PIPE(AFETCH_FLT(g_h + ar * HH + kf),
             BFETCH_FLT((n0 + br) < AA ? h2aW + (size_t)(n0 + br) * HH + kf
                                       : fbW + (size_t)(n0 + br - AA) * HH + kf),
             0, HH / 32, t);
    #pragma unroll
    for (int nt = 0; nt < 8; ++nt) {
        int col = n0 + nh * 64 + nt * 8 + 2 * tig;
        int r0 = mw * 16 + g, r1 = r0 + 8;
        float v[4] = {c[nt][0], c[nt][1], c[nt][2], c[nt][3]};
        int rr[4] = {r0, r0, r1, r1};
        int cc[4] = {col, col + 1, col, col + 1};
        #pragma unroll
        for (int q = 0; q < 4; ++q) {
            if (cc[q] < AA) g_att2F[rr[q] * AA + cc[q]] = v[q];
            else {
                int e = cc[q] - AA;
                g_gateF[rr[q] * ENC + e] = sigmf(v[q] + fbb[e]);
            }
        }
    }
}

// ---------------- score + softmax + alpha ----------------
__global__ __launch_bounds__(512) void k_score(const float* __restrict__ attW,
                                               const float* __restrict__ attb,
                                               float* __restrict__ out, size_t cap, int t) {
    __shared__ float a2[AA];
    __shared__ float aw[AA];
    __shared__ float sc[PP];
    __shared__ float red[2];
    int b = blockIdx.x, tid = threadIdx.x;
    if (g_dlen[b] <= t) {
        for (int p = tid; p < PP; p += 512) {
            size_t idx = PRED_SZ + (size_t)(b * TT + t) * PP + p;
            if (idx < cap) out[idx] = 0.f;
        }
        return;
    }
    for (int i = tid; i < AA; i += 512) {
        a2[i] = g_att2F[b * AA + i];
        aw[i] = attW[i];
    }
    __syncthreads();
    int w = tid >> 5, lane = tid & 31;
    for (int p = w; p < PP; p += 16) {
        const float* base = g_att1 + (size_t)(b * PP + p) * AA;
        float s = 0.f;
        #pragma unroll 4
        for (int a0 = lane; a0 < AA; a0 += 32) {
            float v = base[a0] + a2[a0];
            s += fmaxf(v, 0.f) * aw[a0];
        }
        #pragma unroll
        for (int o = 16; o; o >>= 1) s += __shfl_down_sync(0xFFFFFFFFu, s, o);
        if (lane == 0) sc[p] = s + attb[0];
    }
    __syncthreads();
    if (w == 0) {
        float mx = -1e30f;
        for (int p = lane; p < PP; p += 32) mx = fmaxf(mx, sc[p]);
        #pragma unroll
        for (int o = 16; o; o >>= 1) mx = fmaxf(mx, __shfl_xor_sync(0xFFFFFFFFu, mx, o));
        float sm = 0.f;
        for (int p = lane; p < PP; p += 32) sm += expf(sc[p] - mx);
        #pragma unroll
        for (int o = 16; o; o >>= 1) sm += __shfl_xor_sync(0xFFFFFFFFu, sm, o);
        if (lane == 0) { red[0] = mx; red[1] = 1.0f / sm; }
    }
    __syncthreads();
    float mx = red[0], inv = red[1];
    for (int p = tid; p < PP; p += 512) {
        float al = expf(sc[p] - mx) * inv;
        g_alpha[b * PP + p] = al;
        size_t idx = PRED_SZ + (size_t)(b * TT + t) * PP + p;
        if (idx < cap) out[idx] = al;
    }
}

// ---------------- ctx: gate * (alpha @ enc) ----------------
__global__ void k_ctx(const float* __restrict__ enc, int t) {
    __shared__ float al[PP];
    int b = blockIdx.x;
    if (g_dlen[b] <= t) return;
    int e = blockIdx.y * 256 + threadIdx.x;
    if (threadIdx.x < PP) al[threadIdx.x] = g_alpha[b * PP + threadIdx.x];
    __syncthreads();
    const float* base = enc + (size_t)g_sidx[b] * PP * ENC + e;
    float s = 0.f;
    #pragma unroll 8
    for (int p = 0; p < PP; ++p) s += al[p] * base[p * ENC];
    g_ctx[b * ENC + e] = g_gateF[b * ENC + e] * s;
}

// ---------------- gates (MMA): [emb|ctx|h] @ [Wih;Whh]^T, K-split x8 ----------------
__global__ __launch_bounds__(256) void k_gates_mma(const int* __restrict__ y32,
                                                   const float* __restrict__ emb,
                                                   const float* __restrict__ Wih,
                                                   const float* __restrict__ Whh,
                                                   int t) {
    __shared__ int tokOff[64];
    if (threadIdx.x < 64) {
        int tok = y32[(g_sidx[threadIdx.x] * LL + t) * g_ystride];
        tok = max(0, min(tok, VV - 1));
        tokOff[threadIdx.x] = tok * EE;
    }
    __syncthreads();
    int z = blockIdx.z;
    MMA_PIPE(
        AFETCH_FLT(kf < EE ? emb + tokOff[ar] + kf
                   : kf < EE + ENC ? g_ctx + ar * ENC + (kf - EE)
                                   : g_h + ar * HH + (kf - EE - ENC)),
        BFETCH_FLT(kf < EE + ENC ? Wih + (size_t)(n0 + br) * (EE + ENC) + kf
                                 : Whh + (size_t)(n0 + br) * HH + (kf - EE - ENC)),
        z * 192, 12, t);
    float* P = g_gatesP + (size_t)z * BB * 4 * HH;
    #pragma unroll
    for (int nt = 0; nt < 8; ++nt) {
        int col = n0 + nh * 64 + nt * 8 + 2 * tig;
        int r0 = mw * 16 + g, r1 = r0 + 8;
        P[r0 * (4 * HH) + col]     = c[nt][0];
        P[r0 * (4 * HH) + col + 1] = c[nt][1];
        P[r1 * (4 * HH) + col]     = c[nt][2];
        P[r1 * (4 * HH) + col + 1] = c[nt][3];
    }
}

// ---------------- LSTM: reduce partials, update h/c ----------------
__global__ void k_lstm(const float* __restrict__ bih, const float* __restrict__ bhh, int t) {
    int b = blockIdx.x, j = threadIdx.x;   // 512 threads
    if (g_dlen[b] <= t) return;
    float gs[4];
    #pragma unroll
    for (int gI = 0; gI < 4; ++gI) {
        int n = gI * HH + j;
        float s = bih[n] + bhh[n];
        #pragma unroll
        for (int z = 0; z < SP_GT; ++z)
            s += g_gatesP[((size_t)z * BB + b) * (4 * HH) + n];
        gs[gI] = s;
    }
    float ig = sigmf(gs[0]);
    float fg = sigmf(gs[1]);
    float gg = tanhf(gs[2]);
    float og = sigmf(gs[3]);
    float cv = fg * g_c[b * HH + j] + ig * gg;
    g_c[b * HH + j] = cv;
    g_h[b * HH + j] = og * tanhf(cv);
}

// ---------------- logits (MMA) + masked bounded write ----------------
__global__ __launch_bounds__(256) void k_logits_mma(const float* __restrict__ fcW,
                                                    const float* __restrict__ fcb,
                                                    float* __restrict__ out, size_t cap, int t) {
    MMA_PIPE(AFETCH_FLT(g_h + ar * HH + kf),
             BFETCH_FLT(fcW + (size_t)(n0 + br) * HH + kf),
             0, HH / 32, t);
    #pragma unroll
    for (int nt = 0; nt < 8; ++nt) {
        int col = n0 + nh * 64 + nt * 8 + 2 * tig;
        int r0 = mw * 16 + g, r1 = r0 + 8;
        bool act0 = g_dlen[r0] > t, act1 = g_dlen[r1] > t;
        size_t i00 = ((size_t)r0 * TT + t) * VV + col;
        size_t i10 = ((size_t)r1 * TT + t) * VV + col;
        if (i00 + 1 < cap) {
            out[i00]     = act0 ? c[nt][0] + fcb[col]     : 0.f;
            out[i00 + 1] = act0 ? c[nt][1] + fcb[col + 1] : 0.f;
        }
        if (i10 + 1 < cap) {
            out[i10]     = act1 ? c[nt][2] + fcb[col]     : 0.f;
            out[i10 + 1] = act1 ? c[nt][3] + fcb[col + 1] : 0.f;
        }
    }
}

// ---------------- launch ----------------
extern "C" void kernel_launch(void* const* d_in, const int* in_sizes, int n_in,
                              void* d_out, int out_size) {
    if (n_in < 19) return;
    const float* enc  = (const float*)d_in[0];
    const int*   y32  = (const int*)d_in[1];
    const float* emb  = (const float*)d_in[2];
    const float* e2aW = (const float*)d_in[3];
    const float* h2aW = (const float*)d_in[4];
    const float* attW = (const float*)d_in[5];
    const float* attb = (const float*)d_in[6];
    const float* fbW  = (const float*)d_in[7];
    const float* fbb  = (const float*)d_in[8];
    const float* Wih  = (const float*)d_in[9];
    const float* bih  = (const float*)d_in[10];
    const float* Whh  = (const float*)d_in[11];
    const float* bhh  = (const float*)d_in[12];
    const float* fcW  = (const float*)d_in[13];
    const float* fcb  = (const float*)d_in[14];
    const float* ihW  = (const float*)d_in[15];
    const float* ihb  = (const float*)d_in[16];
    const float* icW  = (const float*)d_in[17];
    const float* icb  = (const float*)d_in[18];

    float* out = (float*)d_out;
    size_t cap = (size_t)out_size;

    static int attr_done = 0;
    if (!attr_done) {
        cudaFuncSetAttribute(k_att1_mma,   cudaFuncAttributeMaxDynamicSharedMemorySize, SM_BYTES);
        cudaFuncSetAttribute(k_hw,         cudaFuncAttributeMaxDynamicSharedMemorySize, SM_BYTES);
        cudaFuncSetAttribute(k_gates_mma,  cudaFuncAttributeMaxDynamicSharedMemorySize, SM_BYTES);
        cudaFuncSetAttribute(k_logits_mma, cudaFuncAttributeMaxDynamicSharedMemorySize, SM_BYTES);
        attr_done = 1;
    }

    // preamble
    k_sort<<<1, 64>>>(y32, out, cap);
    k_mean<<<dim3(BB, ENC / 256), 256>>>(enc);
    k_init_gemm<<<dim3(1024 / TN, 1, SP_INIT), 256>>>(ihW, icW);
    k_init_red<<<BB, 1024>>>(ihb, icb);
    k_att1_mma<<<dim3(AA / 128, (BB * PP) / 64), 256, SM_BYTES>>>(enc, e2aW);

    for (int t = 0; t < TT; ++t) {
        k_hw<<<2560 / 128, 256, SM_BYTES>>>(h2aW, fbW, fbb, t);
        k_score<<<BB, 512>>>(attW, attb, out, cap, t);
        k_ctx<<<dim3(BB, ENC / 256), 256>>>(enc, t);
        k_gates_mma<<<dim3((4 * HH) / 128, 1, SP_GT), 256, SM_BYTES>>>(y32, emb, Wih, Whh, t);
        k_lstm<<<BB, HH>>>(bih, bhh, t);
        k_logits_mma<<<VV / 128, 256, SM_BYTES>>>(fcW, fcb, out, cap, t);
    }
}

// round 15
// speedup vs baseline: 1.2230x; 1.1254x over previous
#include <cuda_runtime.h>
#include <cuda_bf16.h>

// Problem dims (fixed)
#define BB 64
#define PP 196
#define ENC 2048
#define LL 20
#define TT 19
#define VV 32000
#define HH 512
#define EE 512
#define AA 512

#define PRED_SZ ((size_t)BB * TT * VV)
#define ALPHA_SZ ((size_t)BB * TT * PP)

// FFMA GEMM tile config (init kernel)
#define TM 64
#define TN 128
#define TK 16
#define SP_INIT 8
#define SP_GT   8

// smem layout for MMA pipe (u32 words): per buffer 6528 = Ah(1088)+Al(1088)+Bh(2176)+Bl(2176)
#define SM_BUF   6528
#define SM_AL    1088
#define SM_BH    2176
#define SM_BL    4352
#define SM_BYTES (2 * SM_BUF * 4)

// ---------------- scratch (device globals; no allocation) ----------------
__device__ int   g_sidx[BB];
__device__ int   g_dlen[BB];
__device__ int   g_ystride;
__device__ float g_mean[BB * ENC];
__device__ float g_h[BB * HH];
__device__ float g_c[BB * HH];
__device__ float g_hall[TT * BB * HH];            // h history (2.5 MB)
__device__ float g_att1[BB * PP * AA];            // 25.7 MB
__device__ float g_alpha[BB * PP];
__device__ float g_att2F[BB * AA];
__device__ float g_gateF[BB * ENC];
__device__ float g_ctx[BB * ENC];
__device__ float g_initP[SP_INIT * BB * 1024];
__device__ float g_gatesP[SP_GT * BB * 4 * HH];

__device__ __forceinline__ float sigmf(float x) { return 1.0f / (1.0f + expf(-x)); }

#define LD4(p)  (*(const float4*)&(p))

// ---------------- fast truncation bf16 split (hi = trunc, lo = trunc(residual)) ----------------
__device__ __forceinline__ void fsplit2(float x0, float x1, unsigned& hi, unsigned& lo) {
    unsigned u0 = __float_as_uint(x0), u1 = __float_as_uint(x1);
    hi = __byte_perm(u0, u1, 0x7632);
    float l0 = x0 - __uint_as_float(u0 & 0xFFFF0000u);   // exact residual
    float l1 = x1 - __uint_as_float(u1 & 0xFFFF0000u);
    lo = __byte_perm(__float_as_uint(l0), __float_as_uint(l1), 0x7632);
}

__device__ __forceinline__ void mma_bf16(float c[4], unsigned a0, unsigned a1,
                                         unsigned a2, unsigned a3,
                                         unsigned b0, unsigned b1) {
    asm volatile(
        "mma.sync.aligned.m16n8k16.row.col.f32.bf16.bf16.f32 "
        "{%0,%1,%2,%3},{%4,%5,%6,%7},{%8,%9},{%0,%1,%2,%3};"
        : "+f"(c[0]), "+f"(c[1]), "+f"(c[2]), "+f"(c[3])
        : "r"(a0), "r"(a1), "r"(a2), "r"(a3), "r"(b0), "r"(b1));
}

// ---------------- MMA pipeline: 64x128 tile, K chunks of 32, ping-pong 1-sync ----------------
#define MMA_PIPE(AFETCH, BFETCH, KC2START, NCHUNKS, TMASK)                      \
    extern __shared__ unsigned smem_u[];                                        \
    int tid = threadIdx.x;                                                      \
    int n0 = blockIdx.x * 128;                                                  \
    int warp = tid >> 5, lane = tid & 31;                                       \
    int mw = warp >> 1, nh = warp & 1;                                          \
    int g = lane >> 2, tig = lane & 3;                                          \
    int ar = tid >> 2, aq = tid & 3;                                            \
    int br = tid >> 1, bq = tid & 1;                                            \
    int myact = (g_dlen[mw * 16] > (TMASK));                                    \
    float c[8][4];                                                              \
    _Pragma("unroll")                                                           \
    for (int i = 0; i < 8; ++i) c[i][0] = c[i][1] = c[i][2] = c[i][3] = 0.f;    \
    uint4 rAu, rAv, rBu0, rBu1, rBv0, rBv1;                                     \
    { int kc2 = (KC2START); AFETCH; BFETCH; }                                   \
    for (int ch = 0; ch < (NCHUNKS); ++ch) {                                    \
        unsigned* sb = smem_u + (ch & 1) * SM_BUF;                              \
        { int aoff = ar * 17 + aq * 4;                                          \
          sb[aoff+0]=rAu.x; sb[aoff+1]=rAu.y; sb[aoff+2]=rAu.z; sb[aoff+3]=rAu.w; \
          sb[SM_AL+aoff+0]=rAv.x; sb[SM_AL+aoff+1]=rAv.y;                       \
          sb[SM_AL+aoff+2]=rAv.z; sb[SM_AL+aoff+3]=rAv.w;                       \
          int boff = SM_BH + br * 17 + bq * 8;                                  \
          sb[boff+0]=rBu0.x; sb[boff+1]=rBu0.y; sb[boff+2]=rBu0.z; sb[boff+3]=rBu0.w; \
          sb[boff+4]=rBu1.x; sb[boff+5]=rBu1.y; sb[boff+6]=rBu1.z; sb[boff+7]=rBu1.w; \
          int loff = boff + (SM_BL - SM_BH);                                    \
          sb[loff+0]=rBv0.x; sb[loff+1]=rBv0.y; sb[loff+2]=rBv0.z; sb[loff+3]=rBv0.w; \
          sb[loff+4]=rBv1.x; sb[loff+5]=rBv1.y; sb[loff+6]=rBv1.z; sb[loff+7]=rBv1.w; } \
        __syncthreads();                                                        \
        if (ch + 1 < (NCHUNKS)) { int kc2 = (KC2START) + (ch + 1) * 16; AFETCH; BFETCH; } \
        if (myact) {                                                            \
            _Pragma("unroll")                                                   \
            for (int ks = 0; ks < 2; ++ks) {                                    \
                int kb = ks * 8;                                                \
                int r0 = mw * 16 + g, r1 = r0 + 8;                              \
                unsigned a0 = sb[r0*17+kb+tig],   a1 = sb[r1*17+kb+tig];        \
                unsigned a2 = sb[r0*17+kb+4+tig], a3 = sb[r1*17+kb+4+tig];      \
                unsigned l0 = sb[SM_AL+r0*17+kb+tig],   l1 = sb[SM_AL+r1*17+kb+tig]; \
                unsigned l2 = sb[SM_AL+r0*17+kb+4+tig], l3 = sb[SM_AL+r1*17+kb+4+tig]; \
                _Pragma("unroll")                                               \
                for (int nt = 0; nt < 8; ++nt) {                                \
                    int colr = nh * 64 + nt * 8 + g;                            \
                    unsigned b0 = sb[SM_BH+colr*17+kb+tig];                     \
                    unsigned b1 = sb[SM_BH+colr*17+kb+4+tig];                   \
                    unsigned lb0 = sb[SM_BL+colr*17+kb+tig];                    \
                    unsigned lb1 = sb[SM_BL+colr*17+kb+4+tig];                  \
                    mma_bf16(c[nt], a0, a1, a2, a3, b0, b1);                    \
                    mma_bf16(c[nt], l0, l1, l2, l3, b0, b1);                    \
                    mma_bf16(c[nt], a0, a1, a2, a3, lb0, lb1);                  \
                }                                                               \
            }                                                                   \
        }                                                                       \
    }

#define BFETCH_FLT(PTRK)                                                        \
    { int kf = 2 * kc2 + bq * 16;                                               \
      const float* pb = (PTRK);                                                 \
      float4 q0 = LD4(pb[0]), q1 = LD4(pb[4]), q2 = LD4(pb[8]), q3 = LD4(pb[12]); \
      fsplit2(q0.x,q0.y,rBu0.x,rBv0.x); fsplit2(q0.z,q0.w,rBu0.y,rBv0.y);       \
      fsplit2(q1.x,q1.y,rBu0.z,rBv0.z); fsplit2(q1.z,q1.w,rBu0.w,rBv0.w);       \
      fsplit2(q2.x,q2.y,rBu1.x,rBv1.x); fsplit2(q2.z,q2.w,rBu1.y,rBv1.y);       \
      fsplit2(q3.x,q3.y,rBu1.z,rBv1.z); fsplit2(q3.z,q3.w,rBu1.w,rBv1.w); }

#define AFETCH_FLT(PTRK)                                                        \
    { int kf = 2 * kc2 + aq * 8;                                                \
      const float* pa = (PTRK);                                                 \
      float4 f0 = LD4(pa[0]), f1 = LD4(pa[4]);                                  \
      fsplit2(f0.x, f0.y, rAu.x, rAv.x); fsplit2(f0.z, f0.w, rAu.y, rAv.y);     \
      fsplit2(f1.x, f1.y, rAu.z, rAv.z); fsplit2(f1.z, f1.w, rAu.w, rAv.w); }

// ---------------- FFMA GEMM body (init only) ----------------
#define GEMM2_BODY(AFETCH4, WFETCH4, KSTART, KTILES)                            \
    __shared__ float As[2][TK][TM + 4];                                         \
    __shared__ float Ws[2][TK][TN + 4];                                         \
    int tid = threadIdx.x;                                                      \
    int tx = tid & 31, ty = tid >> 5;                                           \
    int n0 = blockIdx.x * TN;                                                   \
    int arow = tid >> 2, kq = tid & 3;                                          \
    int brow0 = tid >> 2, brow1 = (tid >> 2) + 64;                              \
    float acc[8][4] = {};                                                       \
    float4 rA, rB0, rB1;                                                        \
    {                                                                           \
        int k = (KSTART) + kq * 4;                                              \
        rA = AFETCH4(arow, k);                                                  \
        rB0 = WFETCH4(brow0, k);                                                \
        rB1 = WFETCH4(brow1, k);                                                \
    }                                                                           \
    As[0][kq * 4 + 0][arow] = rA.x;  As[0][kq * 4 + 1][arow] = rA.y;            \
    As[0][kq * 4 + 2][arow] = rA.z;  As[0][kq * 4 + 3][arow] = rA.w;            \
    Ws[0][kq * 4 + 0][brow0] = rB0.x; Ws[0][kq * 4 + 1][brow0] = rB0.y;         \
    Ws[0][kq * 4 + 2][brow0] = rB0.z; Ws[0][kq * 4 + 3][brow0] = rB0.w;         \
    Ws[0][kq * 4 + 0][brow1] = rB1.x; Ws[0][kq * 4 + 1][brow1] = rB1.y;         \
    Ws[0][kq * 4 + 2][brow1] = rB1.z; Ws[0][kq * 4 + 3][brow1] = rB1.w;         \
    __syncthreads();                                                            \
    for (int tile = 0; tile < (KTILES); ++tile) {                               \
        int buf = tile & 1;                                                     \
        bool more = (tile + 1) < (KTILES);                                      \
        if (more) {                                                             \
            int k = (KSTART) + (tile + 1) * TK + kq * 4;                        \
            rA = AFETCH4(arow, k);                                              \
            rB0 = WFETCH4(brow0, k);                                            \
            rB1 = WFETCH4(brow1, k);                                            \
        }                                                                       \
        _Pragma("unroll")                                                       \
        for (int kk = 0; kk < TK; ++kk) {                                       \
            float4 a0 = *(const float4*)&As[buf][kk][ty * 8];                   \
            float4 a1 = *(const float4*)&As[buf][kk][ty * 8 + 4];               \
            float4 wv = *(const float4*)&Ws[buf][kk][tx * 4];                   \
            float av[8] = {a0.x, a0.y, a0.z, a0.w, a1.x, a1.y, a1.z, a1.w};     \
            float wr[4] = {wv.x, wv.y, wv.z, wv.w};                             \
            _Pragma("unroll")                                                   \
            for (int i = 0; i < 8; ++i)                                         \
                _Pragma("unroll")                                               \
                for (int j = 0; j < 4; ++j) acc[i][j] += av[i] * wr[j];         \
        }                                                                       \
        __syncthreads();                                                        \
        if (more) {                                                             \
            int nb = buf ^ 1;                                                   \
            As[nb][kq * 4 + 0][arow] = rA.x;  As[nb][kq * 4 + 1][arow] = rA.y;  \
            As[nb][kq * 4 + 2][arow] = rA.z;  As[nb][kq * 4 + 3][arow] = rA.w;  \
            Ws[nb][kq * 4 + 0][brow0] = rB0.x; Ws[nb][kq * 4 + 1][brow0] = rB0.y;\
            Ws[nb][kq * 4 + 2][brow0] = rB0.z; Ws[nb][kq * 4 + 3][brow0] = rB0.w;\
            Ws[nb][kq * 4 + 0][brow1] = rB1.x; Ws[nb][kq * 4 + 1][brow1] = rB1.y;\
            Ws[nb][kq * 4 + 2][brow1] = rB1.z; Ws[nb][kq * 4 + 3][brow1] = rB1.w;\
            __syncthreads();                                                    \
        }                                                                       \
    }

// ---------------- sort / layout detect ----------------
__global__ void k_sort(const int* __restrict__ y32, float* __restrict__ out, size_t cap) {
    __shared__ int len[BB];
    __shared__ int stride_s;
    int i = threadIdx.x;
    if (i == 0) {
        int odd = 0;
        for (int l = 0; l < LL; ++l) odd |= (y32[2 * l + 1] != 0);
        stride_s = odd ? 1 : 2;
        g_ystride = stride_s;
    }
    __syncthreads();
    int stride = stride_s;
    if (i < BB) {
        int c = 0;
        for (int l = 0; l < LL; ++l) c += (y32[(i * LL + l) * stride] != 0);
        len[i] = c;
    }
    __syncthreads();
    if (i < BB) {
        int r = 0;
        for (int j = 0; j < BB; ++j)
            r += (len[j] > len[i]) || (len[j] == len[i] && j < i);
        g_sidx[r] = i;
        g_dlen[r] = len[i] - 1;
        size_t base = PRED_SZ + ALPHA_SZ;
        if (base + r < cap)      out[base + r]      = (float)(len[i] - 1);
        if (base + BB + r < cap) out[base + BB + r] = (float)i;
    }
}

// ---------------- mean over P ----------------
__global__ void k_mean(const float* __restrict__ enc) {
    int b = blockIdx.x;
    int e = blockIdx.y * 256 + threadIdx.x;
    const float* base = enc + (size_t)g_sidx[b] * PP * ENC + e;
    float s = 0.f;
    #pragma unroll 8
    for (int p = 0; p < PP; ++p) s += base[p * ENC];
    g_mean[b * ENC + e] = s * (1.0f / PP);
}

// ---------------- init h0/c0 GEMM + reduce ----------------
__global__ __launch_bounds__(256) void k_init_gemm(const float* __restrict__ ihW,
                                                   const float* __restrict__ icW) {
    int z = blockIdx.z;
#define A_INIT(row, k) LD4(g_mean[(row) * ENC + (k)])
#define W_INIT(row, k) ((n0 + (row)) < HH ? LD4(ihW[(n0 + (row)) * ENC + (k)]) \
                                          : LD4(icW[(n0 + (row) - HH) * ENC + (k)]))
    GEMM2_BODY(A_INIT, W_INIT, z * (ENC / SP_INIT), (ENC / SP_INIT) / TK);
    float* P = g_initP + (size_t)z * BB * 1024;
    #pragma unroll
    for (int i = 0; i < 8; ++i) {
        int m = ty * 8 + i;
        *(float4*)&P[m * 1024 + n0 + tx * 4] =
            make_float4(acc[i][0], acc[i][1], acc[i][2], acc[i][3]);
    }
#undef A_INIT
#undef W_INIT
}

__global__ void k_init_red(const float* __restrict__ ihb, const float* __restrict__ icb) {
    int b = blockIdx.x, n = threadIdx.x;    // 1024 threads
    float s = (n < HH) ? ihb[n] : icb[n - HH];
    #pragma unroll
    for (int z = 0; z < SP_INIT; ++z) s += g_initP[((size_t)z * BB + b) * 1024 + n];
    if (n < HH) g_h[b * HH + n] = s;
    else        g_c[b * HH + (n - HH)] = s;
}

// ---------------- att1 (MMA): enc_sorted @ e2aW^T ----------------
__global__ __launch_bounds__(256) void k_att1_mma(const float* __restrict__ enc,
                                                  const float* __restrict__ e2aW) {
    __shared__ int rowOff[64];
    int m0 = blockIdx.y * 64;
    if (threadIdx.x < 64) {
        int m = m0 + threadIdx.x;
        int b = m / PP, p = m % PP;
        rowOff[threadIdx.x] = (g_sidx[b] * PP + p) * ENC;
    }
    __syncthreads();
    MMA_PIPE(AFETCH_FLT(enc + rowOff[ar] + kf),
             BFETCH_FLT(e2aW + (size_t)(n0 + br) * ENC + kf),
             0, ENC / 32, -1);
    #pragma unroll
    for (int nt = 0; nt < 8; ++nt) {
        int col = n0 + nh * 64 + nt * 8 + 2 * tig;
        int r0 = mw * 16 + g, r1 = r0 + 8;
        g_att1[(size_t)(m0 + r0) * AA + col]     = c[nt][0];
        g_att1[(size_t)(m0 + r0) * AA + col + 1] = c[nt][1];
        g_att1[(size_t)(m0 + r1) * AA + col]     = c[nt][2];
        g_att1[(size_t)(m0 + r1) * AA + col + 1] = c[nt][3];
    }
}

// ---------------- hW (MMA): h @ [h2aW;fbW]^T -> att2F + gateF(sigmoid) ----------------
__global__ __launch_bounds__(256) void k_hw(const float* __restrict__ h2aW,
                                            const float* __restrict__ fbW,
                                            const float* __restrict__ fbb, int t) {
    MMA_PIPE(AFETCH_FLT(g_h + ar * HH + kf),
             BFETCH_FLT((n0 + br) < AA ? h2aW + (size_t)(n0 + br) * HH + kf
                                       : fbW + (size_t)(n0 + br - AA) * HH + kf),
             0, HH / 32, t);
    #pragma unroll
    for (int nt = 0; nt < 8; ++nt) {
        int col = n0 + nh * 64 + nt * 8 + 2 * tig;
        int r0 = mw * 16 + g, r1 = r0 + 8;
        float v[4] = {c[nt][0], c[nt][1], c[nt][2], c[nt][3]};
        int rr[4] = {r0, r0, r1, r1};
        int cc[4] = {col, col + 1, col, col + 1};
        #pragma unroll
        for (int q = 0; q < 4; ++q) {
            if (cc[q] < AA) g_att2F[rr[q] * AA + cc[q]] = v[q];
            else {
                int e = cc[q] - AA;
                g_gateF[rr[q] * ENC + e] = sigmf(v[q] + fbb[e]);
            }
        }
    }
}

// ---------------- score + softmax + alpha ----------------
__global__ __launch_bounds__(512) void k_score(const float* __restrict__ attW,
                                               const float* __restrict__ attb,
                                               float* __restrict__ out, size_t cap, int t) {
    __shared__ float a2[AA];
    __shared__ float aw[AA];
    __shared__ float sc[PP];
    __shared__ float red[2];
    int b = blockIdx.x, tid = threadIdx.x;
    if (g_dlen[b] <= t) {
        for (int p = tid; p < PP; p += 512) {
            size_t idx = PRED_SZ + (size_t)(b * TT + t) * PP + p;
            if (idx < cap) out[idx] = 0.f;
        }
        return;
    }
    for (int i = tid; i < AA; i += 512) {
        a2[i] = g_att2F[b * AA + i];
        aw[i] = attW[i];
    }
    __syncthreads();
    int w = tid >> 5, lane = tid & 31;
    for (int p = w; p < PP; p += 16) {
        const float* base = g_att1 + (size_t)(b * PP + p) * AA;
        float s = 0.f;
        #pragma unroll 4
        for (int a0 = lane; a0 < AA; a0 += 32) {
            float v = base[a0] + a2[a0];
            s += fmaxf(v, 0.f) * aw[a0];
        }
        #pragma unroll
        for (int o = 16; o; o >>= 1) s += __shfl_down_sync(0xFFFFFFFFu, s, o);
        if (lane == 0) sc[p] = s + attb[0];
    }
    __syncthreads();
    if (w == 0) {
        float mx = -1e30f;
        for (int p = lane; p < PP; p += 32) mx = fmaxf(mx, sc[p]);
        #pragma unroll
        for (int o = 16; o; o >>= 1) mx = fmaxf(mx, __shfl_xor_sync(0xFFFFFFFFu, mx, o));
        float sm = 0.f;
        for (int p = lane; p < PP; p += 32) sm += expf(sc[p] - mx);
        #pragma unroll
        for (int o = 16; o; o >>= 1) sm += __shfl_xor_sync(0xFFFFFFFFu, sm, o);
        if (lane == 0) { red[0] = mx; red[1] = 1.0f / sm; }
    }
    __syncthreads();
    float mx = red[0], inv = red[1];
    for (int p = tid; p < PP; p += 512) {
        float al = expf(sc[p] - mx) * inv;
        g_alpha[b * PP + p] = al;
        size_t idx = PRED_SZ + (size_t)(b * TT + t) * PP + p;
        if (idx < cap) out[idx] = al;
    }
}

// ---------------- ctx: gate * (alpha @ enc) ----------------
__global__ void k_ctx(const float* __restrict__ enc, int t) {
    __shared__ float al[PP];
    int b = blockIdx.x;
    if (g_dlen[b] <= t) return;
    int e = blockIdx.y * 256 + threadIdx.x;
    if (threadIdx.x < PP) al[threadIdx.x] = g_alpha[b * PP + threadIdx.x];
    __syncthreads();
    const float* base = enc + (size_t)g_sidx[b] * PP * ENC + e;
    float s = 0.f;
    #pragma unroll 8
    for (int p = 0; p < PP; ++p) s += al[p] * base[p * ENC];
    g_ctx[b * ENC + e] = g_gateF[b * ENC + e] * s;
}

// ---------------- gates (MMA): [emb|ctx|h] @ [Wih;Whh]^T, K-split x8 ----------------
__global__ __launch_bounds__(256) void k_gates_mma(const int* __restrict__ y32,
                                                   const float* __restrict__ emb,
                                                   const float* __restrict__ Wih,
                                                   const float* __restrict__ Whh,
                                                   int t) {
    __shared__ int tokOff[64];
    if (threadIdx.x < 64) {
        int tok = y32[(g_sidx[threadIdx.x] * LL + t) * g_ystride];
        tok = max(0, min(tok, VV - 1));
        tokOff[threadIdx.x] = tok * EE;
    }
    __syncthreads();
    int z = blockIdx.z;
    MMA_PIPE(
        AFETCH_FLT(kf < EE ? emb + tokOff[ar] + kf
                   : kf < EE + ENC ? g_ctx + ar * ENC + (kf - EE)
                                   : g_h + ar * HH + (kf - EE - ENC)),
        BFETCH_FLT(kf < EE + ENC ? Wih + (size_t)(n0 + br) * (EE + ENC) + kf
                                 : Whh + (size_t)(n0 + br) * HH + (kf - EE - ENC)),
        z * 192, 12, t);
    float* P = g_gatesP + (size_t)z * BB * 4 * HH;
    #pragma unroll
    for (int nt = 0; nt < 8; ++nt) {
        int col = n0 + nh * 64 + nt * 8 + 2 * tig;
        int r0 = mw * 16 + g, r1 = r0 + 8;
        P[r0 * (4 * HH) + col]     = c[nt][0];
        P[r0 * (4 * HH) + col + 1] = c[nt][1];
        P[r1 * (4 * HH) + col]     = c[nt][2];
        P[r1 * (4 * HH) + col + 1] = c[nt][3];
    }
}

// ---------------- LSTM: reduce partials, update h/c, record h history ----------------
__global__ void k_lstm(const float* __restrict__ bih, const float* __restrict__ bhh, int t) {
    int b = blockIdx.x, j = threadIdx.x;   // 512 threads
    float* hall = g_hall + ((size_t)t * BB + b) * HH;
    if (g_dlen[b] <= t) {                  // frozen row: record current h
        hall[j] = g_h[b * HH + j];
        return;
    }
    float gs[4];
    #pragma unroll
    for (int gI = 0; gI < 4; ++gI) {
        int n = gI * HH + j;
        float s = bih[n] + bhh[n];
        #pragma unroll
        for (int z = 0; z < SP_GT; ++z)
            s += g_gatesP[((size_t)z * BB + b) * (4 * HH) + n];
        gs[gI] = s;
    }
    float ig = sigmf(gs[0]);
    float fg = sigmf(gs[1]);
    float gg = tanhf(gs[2]);
    float og = sigmf(gs[3]);
    float cv = fg * g_c[b * HH + j] + ig * gg;
    g_c[b * HH + j] = cv;
    float h = og * tanhf(cv);
    g_h[b * HH + j] = h;
    hall[j] = h;
}

// ---------------- final logits GEMM: [19*64, 512] @ fcW^T, masked write ----------------
__global__ __launch_bounds__(256) void k_logits_fin(const float* __restrict__ fcW,
                                                    const float* __restrict__ fcb,
                                                    float* __restrict__ out, size_t cap) {
    int t = blockIdx.y;
    MMA_PIPE(AFETCH_FLT(g_hall + ((size_t)t * BB + ar) * HH + kf),
             BFETCH_FLT(fcW + (size_t)(n0 + br) * HH + kf),
             0, HH / 32, t);
    #pragma unroll
    for (int nt = 0; nt < 8; ++nt) {
        int col = n0 + nh * 64 + nt * 8 + 2 * tig;
        int r0 = mw * 16 + g, r1 = r0 + 8;
        bool act0 = g_dlen[r0] > t, act1 = g_dlen[r1] > t;
        size_t i00 = ((size_t)r0 * TT + t) * VV + col;
        size_t i10 = ((size_t)r1 * TT + t) * VV + col;
        if (i00 + 1 < cap) {
            out[i00]     = act0 ? c[nt][0] + fcb[col]     : 0.f;
            out[i00 + 1] = act0 ? c[nt][1] + fcb[col + 1] : 0.f;
        }
        if (i10 + 1 < cap) {
            out[i10]     = act1 ? c[nt][2] + fcb[col]     : 0.f;
            out[i10 + 1] = act1 ? c[nt][3] + fcb[col + 1] : 0.f;
        }
    }
}

// ---------------- launch ----------------
extern "C" void kernel_launch(void* const* d_in, const int* in_sizes, int n_in,
                              void* d_out, int out_size) {
    if (n_in < 19) return;
    const float* enc  = (const float*)d_in[0];
    const int*   y32  = (const int*)d_in[1];
    const float* emb  = (const float*)d_in[2];
    const float* e2aW = (const float*)d_in[3];
    const float* h2aW = (const float*)d_in[4];
    const float* attW = (const float*)d_in[5];
    const float* attb = (const float*)d_in[6];
    const float* fbW  = (const float*)d_in[7];
    const float* fbb  = (const float*)d_in[8];
    const float* Wih  = (const float*)d_in[9];
    const float* bih  = (const float*)d_in[10];
    const float* Whh  = (const float*)d_in[11];
    const float* bhh  = (const float*)d_in[12];
    const float* fcW  = (const float*)d_in[13];
    const float* fcb  = (const float*)d_in[14];
    const float* ihW  = (const float*)d_in[15];
    const float* ihb  = (const float*)d_in[16];
    const float* icW  = (const float*)d_in[17];
    const float* icb  = (const float*)d_in[18];

    float* out = (float*)d_out;
    size_t cap = (size_t)out_size;

    static int attr_done = 0;
    if (!attr_done) {
        cudaFuncSetAttribute(k_att1_mma,   cudaFuncAttributeMaxDynamicSharedMemorySize, SM_BYTES);
        cudaFuncSetAttribute(k_hw,         cudaFuncAttributeMaxDynamicSharedMemorySize, SM_BYTES);
        cudaFuncSetAttribute(k_gates_mma,  cudaFuncAttributeMaxDynamicSharedMemorySize, SM_BYTES);
        cudaFuncSetAttribute(k_logits_fin, cudaFuncAttributeMaxDynamicSharedMemorySize, SM_BYTES);
        attr_done = 1;
    }

    // preamble
    k_sort<<<1, 64>>>(y32, out, cap);
    k_mean<<<dim3(BB, ENC / 256), 256>>>(enc);
    k_init_gemm<<<dim3(1024 / TN, 1, SP_INIT), 256>>>(ihW, icW);
    k_init_red<<<BB, 1024>>>(ihb, icb);
    k_att1_mma<<<dim3(AA / 128, (BB * PP) / 64), 256, SM_BYTES>>>(enc, e2aW);

    // recurrent loop (no vocabulary projection inside)
    for (int t = 0; t < TT; ++t) {
        k_hw<<<2560 / 128, 256, SM_BYTES>>>(h2aW, fbW, fbb, t);
        k_score<<<BB, 512>>>(attW, attb, out, cap, t);
        k_ctx<<<dim3(BB, ENC / 256), 256>>>(enc, t);
        k_gates_mma<<<dim3((4 * HH) / 128, 1, SP_GT), 256, SM_BYTES>>>(y32, emb, Wih, Whh, t);
        k_lstm<<<BB, HH>>>(bih, bhh, t);
    }

    // one big deferred vocabulary projection: fcW read once
    k_logits_fin<<<dim3(VV / 128, TT), 256, SM_BYTES>>>(fcW, fcb, out, cap);
}

// round 16
// speedup vs baseline: 1.2671x; 1.0361x over previous
#include <cuda_runtime.h>
#include <cuda_bf16.h>

// Problem dims (fixed)
#define BB 64
#define PP 196
#define ENC 2048
#define LL 20
#define TT 19
#define VV 32000
#define HH 512
#define EE 512
#define AA 512

#define PRED_SZ ((size_t)BB * TT * VV)
#define ALPHA_SZ ((size_t)BB * TT * PP)

// FFMA GEMM tile config (init kernel)
#define TM 64
#define TN 128
#define TK 16
#define SP_INIT 8
#define SP_GT   8

// old MMA pipe smem (u32 words)
#define SM_BUF   6528
#define SM_AL    1088
#define SM_BH    2176
#define SM_BL    4352
#define SM_BYTES (2 * SM_BUF * 4)

// new 128x128 pipe smem (u32 words): Ah[128][20] Al Bh Bl
#define SM2_AH   0
#define SM2_AL   2560
#define SM2_BH   5120
#define SM2_BL   7680
#define SM2_BUF  10240
#define SM2_BYTES (2 * SM2_BUF * 4)   // 81920

// ---------------- scratch (device globals; no allocation) ----------------
__device__ int   g_sidx[BB];
__device__ int   g_dlen[BB];
__device__ int   g_ystride;
__device__ float g_mean[BB * ENC];
__device__ float g_h[BB * HH];
__device__ float g_c[BB * HH];
__device__ float g_hall[TT * BB * HH];            // h history (2.5 MB)
__device__ float g_att1[BB * PP * AA];            // 25.7 MB
__device__ float g_alpha[BB * PP];
__device__ float g_att2F[BB * AA];
__device__ float g_gateF[BB * ENC];
__device__ float g_ctx[BB * ENC];
__device__ float g_initP[SP_INIT * BB * 1024];
__device__ float g_gatesP[SP_GT * BB * 4 * HH];

__device__ __forceinline__ float sigmf(float x) { return 1.0f / (1.0f + expf(-x)); }

#define LD4(p)  (*(const float4*)&(p))

// ---------------- fast truncation bf16 split ----------------
__device__ __forceinline__ void fsplit2(float x0, float x1, unsigned& hi, unsigned& lo) {
    unsigned u0 = __float_as_uint(x0), u1 = __float_as_uint(x1);
    hi = __byte_perm(u0, u1, 0x7632);
    float l0 = x0 - __uint_as_float(u0 & 0xFFFF0000u);
    float l1 = x1 - __uint_as_float(u1 & 0xFFFF0000u);
    lo = __byte_perm(__float_as_uint(l0), __float_as_uint(l1), 0x7632);
}

__device__ __forceinline__ void mma_bf16(float c[4], unsigned a0, unsigned a1,
                                         unsigned a2, unsigned a3,
                                         unsigned b0, unsigned b1) {
    asm volatile(
        "mma.sync.aligned.m16n8k16.row.col.f32.bf16.bf16.f32 "
        "{%0,%1,%2,%3},{%4,%5,%6,%7},{%8,%9},{%0,%1,%2,%3};"
        : "+f"(c[0]), "+f"(c[1]), "+f"(c[2]), "+f"(c[3])
        : "r"(a0), "r"(a1), "r"(a2), "r"(a3), "r"(b0), "r"(b1));
}

#define LDSM4(d, addr)                                                          \
    asm volatile("ldmatrix.sync.aligned.m8n8.x4.shared.b16 {%0,%1,%2,%3}, [%4];"\
        : "=r"((d)[0]), "=r"((d)[1]), "=r"((d)[2]), "=r"((d)[3]) : "r"(addr));

// split 16 fp32 -> 8 hi u32 + 8 lo u32
#define FETCH16(PTR, U0, U1, V0, V1)                                            \
    { const float* pz = (PTR);                                                  \
      float4 z0 = LD4(pz[0]), z1 = LD4(pz[4]), z2 = LD4(pz[8]), z3 = LD4(pz[12]); \
      fsplit2(z0.x,z0.y,U0.x,V0.x); fsplit2(z0.z,z0.w,U0.y,V0.y);               \
      fsplit2(z1.x,z1.y,U0.z,V0.z); fsplit2(z1.z,z1.w,U0.w,V0.w);               \
      fsplit2(z2.x,z2.y,U1.x,V1.x); fsplit2(z2.z,z2.w,U1.y,V1.y);               \
      fsplit2(z3.x,z3.y,U1.z,V1.z); fsplit2(z3.z,z3.w,U1.w,V1.w); }

// ---------------- PIPE2: 128x128 tile, warp 32x64, ldmatrix, ping-pong ----------------
// AFETCH/BFETCH: statements using kc2,r2,q2; fill rAu0..rAv1 / rBu0..rBv1 (row r2, 16 floats at q2*16).
#define MMA_PIPE2(AFETCH, BFETCH, NCHUNKS, ACTEXPR)                             \
    extern __shared__ unsigned smem_u[];                                        \
    int tid = threadIdx.x;                                                      \
    int n0 = blockIdx.x * 128;                                                  \
    int warp = tid >> 5, lane = tid & 31;                                       \
    int mw2 = warp >> 1, nh = warp & 1;                                         \
    int g = lane >> 2, tig = lane & 3;                                          \
    int r2 = tid >> 1, q2 = tid & 1;                                            \
    int myact = (ACTEXPR);                                                      \
    unsigned sbase = (unsigned)__cvta_generic_to_shared(smem_u);                \
    unsigned aoff0 = (unsigned)((mw2 * 32 + (lane & 15)) * 20 + (lane >> 4) * 4); \
    unsigned aoff1 = aoff0 + 16 * 20;                                           \
    unsigned boffp = (unsigned)((nh * 64 + (lane & 7) + ((lane & 16) >> 1)) * 20 \
                                + ((lane >> 3) & 1) * 4);                       \
    float c[2][8][4];                                                           \
    _Pragma("unroll")                                                           \
    for (int s = 0; s < 2; ++s)                                                 \
        _Pragma("unroll")                                                       \
        for (int i = 0; i < 8; ++i)                                             \
            c[s][i][0] = c[s][i][1] = c[s][i][2] = c[s][i][3] = 0.f;            \
    uint4 rAu0, rAu1, rAv0, rAv1, rBu0, rBu1, rBv0, rBv1;                       \
    { int kc2 = 0; AFETCH; BFETCH; }                                            \
    for (int ch = 0; ch < (NCHUNKS); ++ch) {                                    \
        unsigned bufo = (ch & 1) * SM2_BUF;                                     \
        { unsigned ao = bufo + r2 * 20 + q2 * 8;                                \
          *(uint4*)(smem_u + ao + SM2_AH)     = rAu0;                           \
          *(uint4*)(smem_u + ao + SM2_AH + 4) = rAu1;                           \
          *(uint4*)(smem_u + ao + SM2_AL)     = rAv0;                           \
          *(uint4*)(smem_u + ao + SM2_AL + 4) = rAv1;                           \
          *(uint4*)(smem_u + ao + SM2_BH)     = rBu0;                           \
          *(uint4*)(smem_u + ao + SM2_BH + 4) = rBu1;                           \
          *(uint4*)(smem_u + ao + SM2_BL)     = rBv0;                           \
          *(uint4*)(smem_u + ao + SM2_BL + 4) = rBv1; }                         \
        __syncthreads();                                                        \
        if (ch + 1 < (NCHUNKS)) { int kc2 = (ch + 1) * 16; AFETCH; BFETCH; }    \
        if (myact) {                                                            \
            _Pragma("unroll")                                                   \
            for (int ks = 0; ks < 2; ++ks) {                                    \
                unsigned kso = ks * 8;                                          \
                unsigned ah0[4], ah1[4], al0[4], al1[4];                        \
                LDSM4(ah0, sbase + (bufo + SM2_AH + aoff0 + kso) * 4);          \
                LDSM4(ah1, sbase + (bufo + SM2_AH + aoff1 + kso) * 4);          \
                LDSM4(al0, sbase + (bufo + SM2_AL + aoff0 + kso) * 4);          \
                LDSM4(al1, sbase + (bufo + SM2_AL + aoff1 + kso) * 4);          \
                _Pragma("unroll")                                               \
                for (int p = 0; p < 4; ++p) {                                   \
                    unsigned bh[4], bl[4];                                      \
                    unsigned bo = boffp + (unsigned)(p * 16 * 20) + kso;        \
                    LDSM4(bh, sbase + (bufo + SM2_BH + bo) * 4);                \
                    LDSM4(bl, sbase + (bufo + SM2_BL + bo) * 4);                \
                    _Pragma("unroll")                                           \
                    for (int q = 0; q < 2; ++q) {                               \
                        int nt = p * 2 + q;                                     \
                        mma_bf16(c[0][nt], ah0[0],ah0[1],ah0[2],ah0[3], bh[2*q], bh[2*q+1]); \
                        mma_bf16(c[0][nt], al0[0],al0[1],al0[2],al0[3], bh[2*q], bh[2*q+1]); \
                        mma_bf16(c[0][nt], ah0[0],ah0[1],ah0[2],ah0[3], bl[2*q], bl[2*q+1]); \
                        mma_bf16(c[1][nt], ah1[0],ah1[1],ah1[2],ah1[3], bh[2*q], bh[2*q+1]); \
                        mma_bf16(c[1][nt], al1[0],al1[1],al1[2],al1[3], bh[2*q], bh[2*q+1]); \
                        mma_bf16(c[1][nt], ah1[0],ah1[1],ah1[2],ah1[3], bl[2*q], bl[2*q+1]); \
                    }                                                           \
                }                                                               \
            }                                                                   \
        }                                                                       \
    }

// ---------------- old MMA pipe (M=64) for hw/gates ----------------
#define MMA_PIPE(AFETCH, BFETCH, KC2START, NCHUNKS, TMASK)                      \
    extern __shared__ unsigned smem_u[];                                        \
    int tid = threadIdx.x;                                                      \
    int n0 = blockIdx.x * 128;                                                  \
    int warp = tid >> 5, lane = tid & 31;                                       \
    int mw = warp >> 1, nh = warp & 1;                                          \
    int g = lane >> 2, tig = lane & 3;                                          \
    int ar = tid >> 2, aq = tid & 3;                                            \
    int br = tid >> 1, bq = tid & 1;                                            \
    int myact = (g_dlen[mw * 16] > (TMASK));                                    \
    float c[8][4];                                                              \
    _Pragma("unroll")                                                           \
    for (int i = 0; i < 8; ++i) c[i][0] = c[i][1] = c[i][2] = c[i][3] = 0.f;    \
    uint4 rAu, rAv, rBu0, rBu1, rBv0, rBv1;                                     \
    { int kc2 = (KC2START); AFETCH; BFETCH; }                                   \
    for (int ch = 0; ch < (NCHUNKS); ++ch) {                                    \
        unsigned* sb = smem_u + (ch & 1) * SM_BUF;                              \
        { int aoff = ar * 17 + aq * 4;                                          \
          sb[aoff+0]=rAu.x; sb[aoff+1]=rAu.y; sb[aoff+2]=rAu.z; sb[aoff+3]=rAu.w; \
          sb[SM_AL+aoff+0]=rAv.x; sb[SM_AL+aoff+1]=rAv.y;                       \
          sb[SM_AL+aoff+2]=rAv.z; sb[SM_AL+aoff+3]=rAv.w;                       \
          int boff = SM_BH + br * 17 + bq * 8;                                  \
          sb[boff+0]=rBu0.x; sb[boff+1]=rBu0.y; sb[boff+2]=rBu0.z; sb[boff+3]=rBu0.w; \
          sb[boff+4]=rBu1.x; sb[boff+5]=rBu1.y; sb[boff+6]=rBu1.z; sb[boff+7]=rBu1.w; \
          int loff = boff + (SM_BL - SM_BH);                                    \
          sb[loff+0]=rBv0.x; sb[loff+1]=rBv0.y; sb[loff+2]=rBv0.z; sb[loff+3]=rBv0.w; \
          sb[loff+4]=rBv1.x; sb[loff+5]=rBv1.y; sb[loff+6]=rBv1.z; sb[loff+7]=rBv1.w; } \
        __syncthreads();                                                        \
        if (ch + 1 < (NCHUNKS)) { int kc2 = (KC2START) + (ch + 1) * 16; AFETCH; BFETCH; } \
        if (myact) {                                                            \
            _Pragma("unroll")                                                   \
            for (int ks = 0; ks < 2; ++ks) {                                    \
                int kb = ks * 8;                                                \
                int r0 = mw * 16 + g, r1 = r0 + 8;                              \
                unsigned a0 = sb[r0*17+kb+tig],   a1 = sb[r1*17+kb+tig];        \
                unsigned a2 = sb[r0*17+kb+4+tig], a3 = sb[r1*17+kb+4+tig];      \
                unsigned l0 = sb[SM_AL+r0*17+kb+tig],   l1 = sb[SM_AL+r1*17+kb+tig]; \
                unsigned l2 = sb[SM_AL+r0*17+kb+4+tig], l3 = sb[SM_AL+r1*17+kb+4+tig]; \
                _Pragma("unroll")                                               \
                for (int nt = 0; nt < 8; ++nt) {                                \
                    int colr = nh * 64 + nt * 8 + g;                            \
                    unsigned b0 = sb[SM_BH+colr*17+kb+tig];                     \
                    unsigned b1 = sb[SM_BH+colr*17+kb+4+tig];                   \
                    unsigned lb0 = sb[SM_BL+colr*17+kb+tig];                    \
                    unsigned lb1 = sb[SM_BL+colr*17+kb+4+tig];                  \
                    mma_bf16(c[nt], a0, a1, a2, a3, b0, b1);                    \
                    mma_bf16(c[nt], l0, l1, l2, l3, b0, b1);                    \
                    mma_bf16(c[nt], a0, a1, a2, a3, lb0, lb1);                  \
                }                                                               \
            }                                                                   \
        }                                                                       \
    }

#define BFETCH_FLT(PTRK)                                                        \
    { int kf = 2 * kc2 + bq * 16;                                               \
      FETCH16(PTRK, rBu0, rBu1, rBv0, rBv1); }

#define AFETCH_FLT(PTRK)                                                        \
    { int kf = 2 * kc2 + aq * 8;                                                \
      const float* pa = (PTRK);                                                 \
      float4 f0 = LD4(pa[0]), f1 = LD4(pa[4]);                                  \
      fsplit2(f0.x, f0.y, rAu.x, rAv.x); fsplit2(f0.z, f0.w, rAu.y, rAv.y);     \
      fsplit2(f1.x, f1.y, rAu.z, rAv.z); fsplit2(f1.z, f1.w, rAu.w, rAv.w); }

// ---------------- FFMA GEMM body (init only) ----------------
#define GEMM2_BODY(AFETCH4, WFETCH4, KSTART, KTILES)                            \
    __shared__ float As[2][TK][TM + 4];                                         \
    __shared__ float Ws[2][TK][TN + 4];                                         \
    int tid = threadIdx.x;                                                      \
    int tx = tid & 31, ty = tid >> 5;                                           \
    int n0 = blockIdx.x * TN;                                                   \
    int arow = tid >> 2, kq = tid & 3;                                          \
    int brow0 = tid >> 2, brow1 = (tid >> 2) + 64;                              \
    float acc[8][4] = {};                                                       \
    float4 rA, rB0, rB1;                                                        \
    {                                                                           \
        int k = (KSTART) + kq * 4;                                              \
        rA = AFETCH4(arow, k);                                                  \
        rB0 = WFETCH4(brow0, k);                                                \
        rB1 = WFETCH4(brow1, k);                                                \
    }                                                                           \
    As[0][kq * 4 + 0][arow] = rA.x;  As[0][kq * 4 + 1][arow] = rA.y;            \
    As[0][kq * 4 + 2][arow] = rA.z;  As[0][kq * 4 + 3][arow] = rA.w;            \
    Ws[0][kq * 4 + 0][brow0] = rB0.x; Ws[0][kq * 4 + 1][brow0] = rB0.y;         \
    Ws[0][kq * 4 + 2][brow0] = rB0.z; Ws[0][kq * 4 + 3][brow0] = rB0.w;         \
    Ws[0][kq * 4 + 0][brow1] = rB1.x; Ws[0][kq * 4 + 1][brow1] = rB1.y;         \
    Ws[0][kq * 4 + 2][brow1] = rB1.z; Ws[0][kq * 4 + 3][brow1] = rB1.w;         \
    __syncthreads();                                                            \
    for (int tile = 0; tile < (KTILES); ++tile) {                               \
        int buf = tile & 1;                                                     \
        bool more = (tile + 1) < (KTILES);                                      \
        if (more) {                                                             \
            int k = (KSTART) + (tile + 1) * TK + kq * 4;                        \
            rA = AFETCH4(arow, k);                                              \
            rB0 = WFETCH4(brow0, k);                                            \
            rB1 = WFETCH4(brow1, k);                                            \
        }                                                                       \
        _Pragma("unroll")                                                       \
        for (int kk = 0; kk < TK; ++kk) {                                       \
            float4 a0 = *(const float4*)&As[buf][kk][ty * 8];                   \
            float4 a1 = *(const float4*)&As[buf][kk][ty * 8 + 4];               \
            float4 wv = *(const float4*)&Ws[buf][kk][tx * 4];                   \
            float av[8] = {a0.x, a0.y, a0.z, a0.w, a1.x, a1.y, a1.z, a1.w};     \
            float wr[4] = {wv.x, wv.y, wv.z, wv.w};                             \
            _Pragma("unroll")                                                   \
            for (int i = 0; i < 8; ++i)                                         \
                _Pragma("unroll")                                               \
                for (int j = 0; j < 4; ++j) acc[i][j] += av[i] * wr[j];         \
        }                                                                       \
        __syncthreads();                                                        \
        if (more) {                                                             \
            int nb = buf ^ 1;                                                   \
            As[nb][kq * 4 + 0][arow] = rA.x;  As[nb][kq * 4 + 1][arow] = rA.y;  \
            As[nb][kq * 4 + 2][arow] = rA.z;  As[nb][kq * 4 + 3][arow] = rA.w;  \
            Ws[nb][kq * 4 + 0][brow0] = rB0.x; Ws[nb][kq * 4 + 1][brow0] = rB0.y;\
            Ws[nb][kq * 4 + 2][brow0] = rB0.z; Ws[nb][kq * 4 + 3][brow0] = rB0.w;\
            Ws[nb][kq * 4 + 0][brow1] = rB1.x; Ws[nb][kq * 4 + 1][brow1] = rB1.y;\
            Ws[nb][kq * 4 + 2][brow1] = rB1.z; Ws[nb][kq * 4 + 3][brow1] = rB1.w;\
            __syncthreads();                                                    \
        }                                                                       \
    }

// ---------------- sort / layout detect ----------------
__global__ void k_sort(const int* __restrict__ y32, float* __restrict__ out, size_t cap) {
    __shared__ int len[BB];
    __shared__ int stride_s;
    int i = threadIdx.x;
    if (i == 0) {
        int odd = 0;
        for (int l = 0; l < LL; ++l) odd |= (y32[2 * l + 1] != 0);
        stride_s = odd ? 1 : 2;
        g_ystride = stride_s;
    }
    __syncthreads();
    int stride = stride_s;
    if (i < BB) {
        int c = 0;
        for (int l = 0; l < LL; ++l) c += (y32[(i * LL + l) * stride] != 0);
        len[i] = c;
    }
    __syncthreads();
    if (i < BB) {
        int r = 0;
        for (int j = 0; j < BB; ++j)
            r += (len[j] > len[i]) || (len[j] == len[i] && j < i);
        g_sidx[r] = i;
        g_dlen[r] = len[i] - 1;
        size_t base = PRED_SZ + ALPHA_SZ;
        if (base + r < cap)      out[base + r]      = (float)(len[i] - 1);
        if (base + BB + r < cap) out[base + BB + r] = (float)i;
    }
}

// ---------------- mean over P ----------------
__global__ void k_mean(const float* __restrict__ enc) {
    int b = blockIdx.x;
    int e = blockIdx.y * 256 + threadIdx.x;
    const float* base = enc + (size_t)g_sidx[b] * PP * ENC + e;
    float s = 0.f;
    #pragma unroll 8
    for (int p = 0; p < PP; ++p) s += base[p * ENC];
    g_mean[b * ENC + e] = s * (1.0f / PP);
}

// ---------------- init h0/c0 GEMM + reduce ----------------
__global__ __launch_bounds__(256) void k_init_gemm(const float* __restrict__ ihW,
                                                   const float* __restrict__ icW) {
    int z = blockIdx.z;
#define A_INIT(row, k) LD4(g_mean[(row) * ENC + (k)])
#define W_INIT(row, k) ((n0 + (row)) < HH ? LD4(ihW[(n0 + (row)) * ENC + (k)]) \
                                          : LD4(icW[(n0 + (row) - HH) * ENC + (k)]))
    GEMM2_BODY(A_INIT, W_INIT, z * (ENC / SP_INIT), (ENC / SP_INIT) / TK);
    float* P = g_initP + (size_t)z * BB * 1024;
    #pragma unroll
    for (int i = 0; i < 8; ++i) {
        int m = ty * 8 + i;
        *(float4*)&P[m * 1024 + n0 + tx * 4] =
            make_float4(acc[i][0], acc[i][1], acc[i][2], acc[i][3]);
    }
#undef A_INIT
#undef W_INIT
}

__global__ void k_init_red(const float* __restrict__ ihb, const float* __restrict__ icb) {
    int b = blockIdx.x, n = threadIdx.x;    // 1024 threads
    float s = (n < HH) ? ihb[n] : icb[n - HH];
    #pragma unroll
    for (int z = 0; z < SP_INIT; ++z) s += g_initP[((size_t)z * BB + b) * 1024 + n];
    if (n < HH) g_h[b * HH + n] = s;
    else        g_c[b * HH + (n - HH)] = s;
}

// ---------------- att1 (PIPE2): enc_sorted @ e2aW^T, 128x128 tiles ----------------
__global__ __launch_bounds__(256) void k_att1_mma(const float* __restrict__ enc,
                                                  const float* __restrict__ e2aW) {
    __shared__ int rowOff[128];
    int m0 = blockIdx.y * 128;
    if (threadIdx.x < 128) {
        int m = m0 + threadIdx.x;
        int b = m / PP, p = m % PP;
        rowOff[threadIdx.x] = (g_sidx[b] * PP + p) * ENC;
    }
    __syncthreads();
#define AF_A1 { int kf = 2 * kc2 + q2 * 16; \
                FETCH16(enc + rowOff[r2] + kf, rAu0, rAu1, rAv0, rAv1); }
#define BF_A1 { int kf = 2 * kc2 + q2 * 16; \
                FETCH16(e2aW + (size_t)(n0 + r2) * ENC + kf, rBu0, rBu1, rBv0, rBv1); }
    MMA_PIPE2(AF_A1, BF_A1, ENC / 32, 1);
    #pragma unroll
    for (int s = 0; s < 2; ++s)
        #pragma unroll
        for (int nt = 0; nt < 8; ++nt) {
            int col = n0 + nh * 64 + nt * 8 + 2 * tig;
            int r0 = m0 + mw2 * 32 + s * 16 + g, r1 = r0 + 8;
            g_att1[(size_t)r0 * AA + col]     = c[s][nt][0];
            g_att1[(size_t)r0 * AA + col + 1] = c[s][nt][1];
            g_att1[(size_t)r1 * AA + col]     = c[s][nt][2];
            g_att1[(size_t)r1 * AA + col + 1] = c[s][nt][3];
        }
#undef AF_A1
#undef BF_A1
}

// ---------------- hW (MMA): h @ [h2aW;fbW]^T -> att2F + gateF(sigmoid) ----------------
__global__ __launch_bounds__(256) void k_hw(const float* __restrict__ h2aW,
                                            const float* __restrict__ fbW,
                                            const float* __restrict__ fbb, int t) {
    MMA_PIPE(AFETCH_FLT(g_h + ar * HH + kf),
             BFETCH_FLT((n0 + br) < AA ? h2aW + (size_t)(n0 + br) * HH + kf
                                       : fbW + (size_t)(n0 + br - AA) * HH + kf),
             0, HH / 32, t);
    #pragma unroll
    for (int nt = 0; nt < 8; ++nt) {
        int col = n0 + nh * 64 + nt * 8 + 2 * tig;
        int r0 = mw * 16 + g, r1 = r0 + 8;
        float v[4] = {c[nt][0], c[nt][1], c[nt][2], c[nt][3]};
        int rr[4] = {r0, r0, r1, r1};
        int cc[4] = {col, col + 1, col, col + 1};
        #pragma unroll
        for (int q = 0; q < 4; ++q) {
            if (cc[q] < AA) g_att2F[rr[q] * AA + cc[q]] = v[q];
            else {
                int e = cc[q] - AA;
                g_gateF[rr[q] * ENC + e] = sigmf(v[q] + fbb[e]);
            }
        }
    }
}

// ---------------- score + softmax + alpha ----------------
__global__ __launch_bounds__(512) void k_score(const float* __restrict__ attW,
                                               const float* __restrict__ attb,
                                               float* __restrict__ out, size_t cap, int t) {
    __shared__ float a2[AA];
    __shared__ float aw[AA];
    __shared__ float sc[PP];
    __shared__ float red[2];
    int b = blockIdx.x, tid = threadIdx.x;
    if (g_dlen[b] <= t) {
        for (int p = tid; p < PP; p += 512) {
            size_t idx = PRED_SZ + (size_t)(b * TT + t) * PP + p;
            if (idx < cap) out[idx] = 0.f;
        }
        return;
    }
    for (int i = tid; i < AA; i += 512) {
        a2[i] = g_att2F[b * AA + i];
        aw[i] = attW[i];
    }
    __syncthreads();
    int w = tid >> 5, lane = tid & 31;
    for (int p = w; p < PP; p += 16) {
        const float* base = g_att1 + (size_t)(b * PP + p) * AA;
        float s = 0.f;
        #pragma unroll 4
        for (int a0 = lane; a0 < AA; a0 += 32) {
            float v = base[a0] + a2[a0];
            s += fmaxf(v, 0.f) * aw[a0];
        }
        #pragma unroll
        for (int o = 16; o; o >>= 1) s += __shfl_down_sync(0xFFFFFFFFu, s, o);
        if (lane == 0) sc[p] = s + attb[0];
    }
    __syncthreads();
    if (w == 0) {
        float mx = -1e30f;
        for (int p = lane; p < PP; p += 32) mx = fmaxf(mx, sc[p]);
        #pragma unroll
        for (int o = 16; o; o >>= 1) mx = fmaxf(mx, __shfl_xor_sync(0xFFFFFFFFu, mx, o));
        float sm = 0.f;
        for (int p = lane; p < PP; p += 32) sm += expf(sc[p] - mx);
        #pragma unroll
        for (int o = 16; o; o >>= 1) sm += __shfl_xor_sync(0xFFFFFFFFu, sm, o);
        if (lane == 0) { red[0] = mx; red[1] = 1.0f / sm; }
    }
    __syncthreads();
    float mx = red[0], inv = red[1];
    for (int p = tid; p < PP; p += 512) {
        float al = expf(sc[p] - mx) * inv;
        g_alpha[b * PP + p] = al;
        size_t idx = PRED_SZ + (size_t)(b * TT + t) * PP + p;
        if (idx < cap) out[idx] = al;
    }
}

// ---------------- ctx: gate * (alpha @ enc) ----------------
__global__ void k_ctx(const float* __restrict__ enc, int t) {
    __shared__ float al[PP];
    int b = blockIdx.x;
    if (g_dlen[b] <= t) return;
    int e = blockIdx.y * 256 + threadIdx.x;
    if (threadIdx.x < PP) al[threadIdx.x] = g_alpha[b * PP + threadIdx.x];
    __syncthreads();
    const float* base = enc + (size_t)g_sidx[b] * PP * ENC + e;
    float s = 0.f;
    #pragma unroll 8
    for (int p = 0; p < PP; ++p) s += al[p] * base[p * ENC];
    g_ctx[b * ENC + e] = g_gateF[b * ENC + e] * s;
}

// ---------------- gates (MMA): [emb|ctx|h] @ [Wih;Whh]^T, K-split x8 ----------------
__global__ __launch_bounds__(256) void k_gates_mma(const int* __restrict__ y32,
                                                   const float* __restrict__ emb,
                                                   const float* __restrict__ Wih,
                                                   const float* __restrict__ Whh,
                                                   int t) {
    __shared__ int tokOff[64];
    if (threadIdx.x < 64) {
        int tok = y32[(g_sidx[threadIdx.x] * LL + t) * g_ystride];
        tok = max(0, min(tok, VV - 1));
        tokOff[threadIdx.x] = tok * EE;
    }
    __syncthreads();
    int z = blockIdx.z;
    MMA_PIPE(
        AFETCH_FLT(kf < EE ? emb + tokOff[ar] + kf
                   : kf < EE + ENC ? g_ctx + ar * ENC + (kf - EE)
                                   : g_h + ar * HH + (kf - EE - ENC)),
        BFETCH_FLT(kf < EE + ENC ? Wih + (size_t)(n0 + br) * (EE + ENC) + kf
                                 : Whh + (size_t)(n0 + br) * HH + (kf - EE - ENC)),
        z * 192, 12, t);
    float* P = g_gatesP + (size_t)z * BB * 4 * HH;
    #pragma unroll
    for (int nt = 0; nt < 8; ++nt) {
        int col = n0 + nh * 64 + nt * 8 + 2 * tig;
        int r0 = mw * 16 + g, r1 = r0 + 8;
        P[r0 * (4 * HH) + col]     = c[nt][0];
        P[r0 * (4 * HH) + col + 1] = c[nt][1];
        P[r1 * (4 * HH) + col]     = c[nt][2];
        P[r1 * (4 * HH) + col + 1] = c[nt][3];
    }
}

// ---------------- LSTM: reduce partials, update h/c, record h history ----------------
__global__ void k_lstm(const float* __restrict__ bih, const float* __restrict__ bhh, int t) {
    int b = blockIdx.x, j = threadIdx.x;   // 512 threads
    float* hall = g_hall + ((size_t)t * BB + b) * HH;
    if (g_dlen[b] <= t) {
        hall[j] = g_h[b * HH + j];
        return;
    }
    float gs[4];
    #pragma unroll
    for (int gI = 0; gI < 4; ++gI) {
        int n = gI * HH + j;
        float s = bih[n] + bhh[n];
        #pragma unroll
        for (int z = 0; z < SP_GT; ++z)
            s += g_gatesP[((size_t)z * BB + b) * (4 * HH) + n];
        gs[gI] = s;
    }
    float ig = sigmf(gs[0]);
    float fg = sigmf(gs[1]);
    float gg = tanhf(gs[2]);
    float og = sigmf(gs[3]);
    float cv = fg * g_c[b * HH + j] + ig * gg;
    g_c[b * HH + j] = cv;
    float h = og * tanhf(cv);
    g_h[b * HH + j] = h;
    hall[j] = h;
}

// ---------------- final logits (PIPE2): [1216,512] @ fcW^T, 128-row tiles ----------------
__global__ __launch_bounds__(256) void k_logits_fin(const float* __restrict__ fcW,
                                                    const float* __restrict__ fcb,
                                                    float* __restrict__ out, size_t cap) {
    int T0 = blockIdx.y;        // 0..9, rows T0*128..+128 (pad beyond 1215)
#define AF_LG { int kf = 2 * kc2 + q2 * 16; \
                int gr = min(T0 * 128 + r2, TT * BB - 1); \
                FETCH16(g_hall + (size_t)gr * HH + kf, rAu0, rAu1, rAv0, rAv1); }
#define BF_LG { int kf = 2 * kc2 + q2 * 16; \
                FETCH16(fcW + (size_t)(n0 + r2) * HH + kf, rBu0, rBu1, rBv0, rBv1); }
    MMA_PIPE2(AF_LG, BF_LG, HH / 32,
              ({ int tw = T0 * 2 + (mw2 >> 1); int bw = (mw2 & 1) * 32;
                 (tw < TT) && (g_dlen[bw] > tw); }));
    #pragma unroll
    for (int s = 0; s < 2; ++s)
        #pragma unroll
        for (int nt = 0; nt < 8; ++nt) {
            int col = n0 + nh * 64 + nt * 8 + 2 * tig;
            int r0 = T0 * 128 + mw2 * 32 + s * 16 + g, r1 = r0 + 8;
            int t0 = r0 >> 6;
            if (t0 >= TT) continue;
            int b0 = r0 & 63, b1 = b0 + 8;
            bool act0 = g_dlen[b0] > t0, act1 = g_dlen[b1] > t0;
            size_t i00 = ((size_t)b0 * TT + t0) * VV + col;
            size_t i10 = ((size_t)b1 * TT + t0) * VV + col;
            if (i00 + 1 < cap) {
                out[i00]     = act0 ? c[s][nt][0] + fcb[col]     : 0.f;
                out[i00 + 1] = act0 ? c[s][nt][1] + fcb[col + 1] : 0.f;
            }
            if (i10 + 1 < cap) {
                out[i10]     = act1 ? c[s][nt][2] + fcb[col]     : 0.f;
                out[i10 + 1] = act1 ? c[s][nt][3] + fcb[col + 1] : 0.f;
            }
        }
#undef AF_LG
#undef BF_LG
}

// ---------------- launch ----------------
extern "C" void kernel_launch(void* const* d_in, const int* in_sizes, int n_in,
                              void* d_out, int out_size) {
    if (n_in < 19) return;
    const float* enc  = (const float*)d_in[0];
    const int*   y32  = (const int*)d_in[1];
    const float* emb  = (const float*)d_in[2];
    const float* e2aW = (const float*)d_in[3];
    const float* h2aW = (const float*)d_in[4];
    const float* attW = (const float*)d_in[5];
    const float* attb = (const float*)d_in[6];
    const float* fbW  = (const float*)d_in[7];
    const float* fbb  = (const float*)d_in[8];
    const float* Wih  = (const float*)d_in[9];
    const float* bih  = (const float*)d_in[10];
    const float* Whh  = (const float*)d_in[11];
    const float* bhh  = (const float*)d_in[12];
    const float* fcW  = (const float*)d_in[13];
    const float* fcb  = (const float*)d_in[14];
    const float* ihW  = (const float*)d_in[15];
    const float* ihb  = (const float*)d_in[16];
    const float* icW  = (const float*)d_in[17];
    const float* icb  = (const float*)d_in[18];

    float* out = (float*)d_out;
    size_t cap = (size_t)out_size;

    static int attr_done = 0;
    if (!attr_done) {
        cudaFuncSetAttribute(k_att1_mma,   cudaFuncAttributeMaxDynamicSharedMemorySize, SM2_BYTES);
        cudaFuncSetAttribute(k_logits_fin, cudaFuncAttributeMaxDynamicSharedMemorySize, SM2_BYTES);
        cudaFuncSetAttribute(k_hw,         cudaFuncAttributeMaxDynamicSharedMemorySize, SM_BYTES);
        cudaFuncSetAttribute(k_gates_mma,  cudaFuncAttributeMaxDynamicSharedMemorySize, SM_BYTES);
        attr_done = 1;
    }

    // preamble
    k_sort<<<1, 64>>>(y32, out, cap);
    k_mean<<<dim3(BB, ENC / 256), 256>>>(enc);
    k_init_gemm<<<dim3(1024 / TN, 1, SP_INIT), 256>>>(ihW, icW);
    k_init_red<<<BB, 1024>>>(ihb, icb);
    k_att1_mma<<<dim3(AA / 128, (BB * PP) / 128), 256, SM2_BYTES>>>(enc, e2aW);

    // recurrent loop (no vocabulary projection inside)
    for (int t = 0; t < TT; ++t) {
        k_hw<<<2560 / 128, 256, SM_BYTES>>>(h2aW, fbW, fbb, t);
        k_score<<<BB, 512>>>(attW, attb, out, cap, t);
        k_ctx<<<dim3(BB, ENC / 256), 256>>>(enc, t);
        k_gates_mma<<<dim3((4 * HH) / 128, 1, SP_GT), 256, SM_BYTES>>>(y32, emb, Wih, Whh, t);
        k_lstm<<<BB, HH>>>(bih, bhh, t);
    }

    // one big deferred vocabulary projection (fcW read once), 128-row tiles
    k_logits_fin<<<dim3(VV / 128, (TT * BB + 127) / 128), 256, SM2_BYTES>>>(fcW, fcb, out, cap);
}

// round 17
// speedup vs baseline: 1.2940x; 1.0213x over previous
#include <cuda_runtime.h>
#include <cuda_bf16.h>
#include <cuda_fp16.h>

// Problem dims (fixed)
#define BB 64
#define PP 196
#define ENC 2048
#define LL 20
#define TT 19
#define VV 32000
#define HH 512
#define EE 512
#define AA 512

#define PRED_SZ ((size_t)BB * TT * VV)
#define ALPHA_SZ ((size_t)BB * TT * PP)

// FFMA GEMM tile config (init kernel)
#define TM 64
#define TN 128
#define TK 16
#define SP_INIT 8
#define SP_GT   8

// old MMA pipe smem (u32 words)
#define SM_BUF   6528
#define SM_AL    1088
#define SM_BH    2176
#define SM_BL    4352
#define SM_BYTES (2 * SM_BUF * 4)

// new 128x128 pipe smem (u32 words): Ah[128][20] Al Bh Bl
#define SM2_AH   0
#define SM2_AL   2560
#define SM2_BH   5120
#define SM2_BL   7680
#define SM2_BUF  10240
#define SM2_BYTES (2 * SM2_BUF * 4)   // 81920

// ---------------- scratch (device globals; no allocation) ----------------
__device__ int   g_sidx[BB];
__device__ int   g_dlen[BB];
__device__ int   g_ystride;
__device__ float g_mean[BB * ENC];
__device__ float g_h[BB * HH];
__device__ float g_c[BB * HH];
__device__ float g_hall[TT * BB * HH];            // h history (2.5 MB)
__device__ float g_att1[BB * PP * AA];            // 25.7 MB
__device__ float g_att2F[BB * AA];
__device__ float g_gateF[BB * ENC];
__device__ float g_ctx[BB * ENC];
__device__ float g_initP[SP_INIT * BB * 1024];
__device__ float g_gatesP[SP_GT * BB * 4 * HH];
__device__ __half g_ench[(size_t)BB * PP * ENC];  // sorted encoder, fp16 (51 MB)

__device__ __forceinline__ float sigmf(float x) { return 1.0f / (1.0f + expf(-x)); }

#define LD4(p)  (*(const float4*)&(p))

// ---------------- fast truncation bf16 split ----------------
__device__ __forceinline__ void fsplit2(float x0, float x1, unsigned& hi, unsigned& lo) {
    unsigned u0 = __float_as_uint(x0), u1 = __float_as_uint(x1);
    hi = __byte_perm(u0, u1, 0x7632);
    float l0 = x0 - __uint_as_float(u0 & 0xFFFF0000u);
    float l1 = x1 - __uint_as_float(u1 & 0xFFFF0000u);
    lo = __byte_perm(__float_as_uint(l0), __float_as_uint(l1), 0x7632);
}

__device__ __forceinline__ void mma_bf16(float c[4], unsigned a0, unsigned a1,
                                         unsigned a2, unsigned a3,
                                         unsigned b0, unsigned b1) {
    asm volatile(
        "mma.sync.aligned.m16n8k16.row.col.f32.bf16.bf16.f32 "
        "{%0,%1,%2,%3},{%4,%5,%6,%7},{%8,%9},{%0,%1,%2,%3};"
        : "+f"(c[0]), "+f"(c[1]), "+f"(c[2]), "+f"(c[3])
        : "r"(a0), "r"(a1), "r"(a2), "r"(a3), "r"(b0), "r"(b1));
}

#define LDSM4(d, addr)                                                          \
    asm volatile("ldmatrix.sync.aligned.m8n8.x4.shared.b16 {%0,%1,%2,%3}, [%4];"\
        : "=r"((d)[0]), "=r"((d)[1]), "=r"((d)[2]), "=r"((d)[3]) : "r"(addr));

// split 16 fp32 -> 8 hi u32 + 8 lo u32
#define FETCH16(PTR, U0, U1, V0, V1)                                            \
    { const float* pz = (PTR);                                                  \
      float4 z0 = LD4(pz[0]), z1 = LD4(pz[4]), z2 = LD4(pz[8]), z3 = LD4(pz[12]); \
      fsplit2(z0.x,z0.y,U0.x,V0.x); fsplit2(z0.z,z0.w,U0.y,V0.y);               \
      fsplit2(z1.x,z1.y,U0.z,V0.z); fsplit2(z1.z,z1.w,U0.w,V0.w);               \
      fsplit2(z2.x,z2.y,U1.x,V1.x); fsplit2(z2.z,z2.w,U1.y,V1.y);               \
      fsplit2(z3.x,z3.y,U1.z,V1.z); fsplit2(z3.z,z3.w,U1.w,V1.w); }

// ---------------- PIPE2: 128x128 tile, warp 32x64, ldmatrix, ping-pong ----------------
#define MMA_PIPE2(AFETCH, BFETCH, NCHUNKS, ACTEXPR)                             \
    extern __shared__ unsigned smem_u[];                                        \
    int tid = threadIdx.x;                                                      \
    int n0 = blockIdx.x * 128;                                                  \
    int warp = tid >> 5, lane = tid & 31;                                       \
    int mw2 = warp >> 1, nh = warp & 1;                                         \
    int g = lane >> 2, tig = lane & 3;                                          \
    int r2 = tid >> 1, q2 = tid & 1;                                            \
    int myact = (ACTEXPR);                                                      \
    unsigned sbase = (unsigned)__cvta_generic_to_shared(smem_u);                \
    unsigned aoff0 = (unsigned)((mw2 * 32 + (lane & 15)) * 20 + (lane >> 4) * 4); \
    unsigned aoff1 = aoff0 + 16 * 20;                                           \
    unsigned boffp = (unsigned)((nh * 64 + (lane & 7) + ((lane & 16) >> 1)) * 20 \
                                + ((lane >> 3) & 1) * 4);                       \
    float c[2][8][4];                                                           \
    _Pragma("unroll")                                                           \
    for (int s = 0; s < 2; ++s)                                                 \
        _Pragma("unroll")                                                       \
        for (int i = 0; i < 8; ++i)                                             \
            c[s][i][0] = c[s][i][1] = c[s][i][2] = c[s][i][3] = 0.f;            \
    uint4 rAu0, rAu1, rAv0, rAv1, rBu0, rBu1, rBv0, rBv1;                       \
    { int kc2 = 0; AFETCH; BFETCH; }                                            \
    for (int ch = 0; ch < (NCHUNKS); ++ch) {                                    \
        unsigned bufo = (ch & 1) * SM2_BUF;                                     \
        { unsigned ao = bufo + r2 * 20 + q2 * 8;                                \
          *(uint4*)(smem_u + ao + SM2_AH)     = rAu0;                           \
          *(uint4*)(smem_u + ao + SM2_AH + 4) = rAu1;                           \
          *(uint4*)(smem_u + ao + SM2_AL)     = rAv0;                           \
          *(uint4*)(smem_u + ao + SM2_AL + 4) = rAv1;                           \
          *(uint4*)(smem_u + ao + SM2_BH)     = rBu0;                           \
          *(uint4*)(smem_u + ao + SM2_BH + 4) = rBu1;                           \
          *(uint4*)(smem_u + ao + SM2_BL)     = rBv0;                           \
          *(uint4*)(smem_u + ao + SM2_BL + 4) = rBv1; }                         \
        __syncthreads();                                                        \
        if (ch + 1 < (NCHUNKS)) { int kc2 = (ch + 1) * 16; AFETCH; BFETCH; }    \
        if (myact) {                                                            \
            _Pragma("unroll")                                                   \
            for (int ks = 0; ks < 2; ++ks) {                                    \
                unsigned kso = ks * 8;                                          \
                unsigned ah0[4], ah1[4], al0[4], al1[4];                        \
                LDSM4(ah0, sbase + (bufo + SM2_AH + aoff0 + kso) * 4);          \
                LDSM4(ah1, sbase + (bufo + SM2_AH + aoff1 + kso) * 4);          \
                LDSM4(al0, sbase + (bufo + SM2_AL + aoff0 + kso) * 4);          \
                LDSM4(al1, sbase + (bufo + SM2_AL + aoff1 + kso) * 4);          \
                _Pragma("unroll")                                               \
                for (int p = 0; p < 4; ++p) {                                   \
                    unsigned bh[4], bl[4];                                      \
                    unsigned bo = boffp + (unsigned)(p * 16 * 20) + kso;        \
                    LDSM4(bh, sbase + (bufo + SM2_BH + bo) * 4);                \
                    LDSM4(bl, sbase + (bufo + SM2_BL + bo) * 4);                \
                    _Pragma("unroll")                                           \
                    for (int q = 0; q < 2; ++q) {                               \
                        int nt = p * 2 + q;                                     \
                        mma_bf16(c[0][nt], ah0[0],ah0[1],ah0[2],ah0[3], bh[2*q], bh[2*q+1]); \
                        mma_bf16(c[0][nt], al0[0],al0[1],al0[2],al0[3], bh[2*q], bh[2*q+1]); \
                        mma_bf16(c[0][nt], ah0[0],ah0[1],ah0[2],ah0[3], bl[2*q], bl[2*q+1]); \
                        mma_bf16(c[1][nt], ah1[0],ah1[1],ah1[2],ah1[3], bh[2*q], bh[2*q+1]); \
                        mma_bf16(c[1][nt], al1[0],al1[1],al1[2],al1[3], bh[2*q], bh[2*q+1]); \
                        mma_bf16(c[1][nt], ah1[0],ah1[1],ah1[2],ah1[3], bl[2*q], bl[2*q+1]); \
                    }                                                           \
                }                                                               \
            }                                                                   \
        }                                                                       \
    }

// ---------------- old MMA pipe (M=64) for hw/gates ----------------
#define MMA_PIPE(AFETCH, BFETCH, KC2START, NCHUNKS, TMASK)                      \
    extern __shared__ unsigned smem_u[];                                        \
    int tid = threadIdx.x;                                                      \
    int n0 = blockIdx.x * 128;                                                  \
    int warp = tid >> 5, lane = tid & 31;                                       \
    int mw = warp >> 1, nh = warp & 1;                                          \
    int g = lane >> 2, tig = lane & 3;                                          \
    int ar = tid >> 2, aq = tid & 3;                                            \
    int br = tid >> 1, bq = tid & 1;                                            \
    int myact = (g_dlen[mw * 16] > (TMASK));                                    \
    float c[8][4];                                                              \
    _Pragma("unroll")                                                           \
    for (int i = 0; i < 8; ++i) c[i][0] = c[i][1] = c[i][2] = c[i][3] = 0.f;    \
    uint4 rAu, rAv, rBu0, rBu1, rBv0, rBv1;                                     \
    { int kc2 = (KC2START); AFETCH; BFETCH; }                                   \
    for (int ch = 0; ch < (NCHUNKS); ++ch) {                                    \
        unsigned* sb = smem_u + (ch & 1) * SM_BUF;                              \
        { int aoff = ar * 17 + aq * 4;                                          \
          sb[aoff+0]=rAu.x; sb[aoff+1]=rAu.y; sb[aoff+2]=rAu.z; sb[aoff+3]=rAu.w; \
          sb[SM_AL+aoff+0]=rAv.x; sb[SM_AL+aoff+1]=rAv.y;                       \
          sb[SM_AL+aoff+2]=rAv.z; sb[SM_AL+aoff+3]=rAv.w;                       \
          int boff = SM_BH + br * 17 + bq * 8;                                  \
          sb[boff+0]=rBu0.x; sb[boff+1]=rBu0.y; sb[boff+2]=rBu0.z; sb[boff+3]=rBu0.w; \
          sb[boff+4]=rBu1.x; sb[boff+5]=rBu1.y; sb[boff+6]=rBu1.z; sb[boff+7]=rBu1.w; \
          int loff = boff + (SM_BL - SM_BH);                                    \
          sb[loff+0]=rBv0.x; sb[loff+1]=rBv0.y; sb[loff+2]=rBv0.z; sb[loff+3]=rBv0.w; \
          sb[loff+4]=rBv1.x; sb[loff+5]=rBv1.y; sb[loff+6]=rBv1.z; sb[loff+7]=rBv1.w; } \
        __syncthreads();                                                        \
        if (ch + 1 < (NCHUNKS)) { int kc2 = (KC2START) + (ch + 1) * 16; AFETCH; BFETCH; } \
        if (myact) {                                                            \
            _Pragma("unroll")                                                   \
            for (int ks = 0; ks < 2; ++ks) {                                    \
                int kb = ks * 8;                                                \
                int r0 = mw * 16 + g, r1 = r0 + 8;                              \
                unsigned a0 = sb[r0*17+kb+tig],   a1 = sb[r1*17+kb+tig];        \
                unsigned a2 = sb[r0*17+kb+4+tig], a3 = sb[r1*17+kb+4+tig];      \
                unsigned l0 = sb[SM_AL+r0*17+kb+tig],   l1 = sb[SM_AL+r1*17+kb+tig]; \
                unsigned l2 = sb[SM_AL+r0*17+kb+4+tig], l3 = sb[SM_AL+r1*17+kb+4+tig]; \
                _Pragma("unroll")                                               \
                for (int nt = 0; nt < 8; ++nt) {                                \
                    int colr = nh * 64 + nt * 8 + g;                            \
                    unsigned b0 = sb[SM_BH+colr*17+kb+tig];                     \
                    unsigned b1 = sb[SM_BH+colr*17+kb+4+tig];                   \
                    unsigned lb0 = sb[SM_BL+colr*17+kb+tig];                    \
                    unsigned lb1 = sb[SM_BL+colr*17+kb+4+tig];                  \
                    mma_bf16(c[nt], a0, a1, a2, a3, b0, b1);                    \
                    mma_bf16(c[nt], l0, l1, l2, l3, b0, b1);                    \
                    mma_bf16(c[nt], a0, a1, a2, a3, lb0, lb1);                  \
                }                                                               \
            }                                                                   \
        }                                                                       \
    }

#define BFETCH_FLT(PTRK)                                                        \
    { int kf = 2 * kc2 + bq * 16;                                               \
      FETCH16(PTRK, rBu0, rBu1, rBv0, rBv1); }

#define AFETCH_FLT(PTRK)                                                        \
    { int kf = 2 * kc2 + aq * 8;                                                \
      const float* pa = (PTRK);                                                 \
      float4 f0 = LD4(pa[0]), f1 = LD4(pa[4]);                                  \
      fsplit2(f0.x, f0.y, rAu.x, rAv.x); fsplit2(f0.z, f0.w, rAu.y, rAv.y);     \
      fsplit2(f1.x, f1.y, rAu.z, rAv.z); fsplit2(f1.z, f1.w, rAu.w, rAv.w); }

// ---------------- FFMA GEMM body (init only) ----------------
#define GEMM2_BODY(AFETCH4, WFETCH4, KSTART, KTILES)                            \
    __shared__ float As[2][TK][TM + 4];                                         \
    __shared__ float Ws[2][TK][TN + 4];                                         \
    int tid = threadIdx.x;                                                      \
    int tx = tid & 31, ty = tid >> 5;                                           \
    int n0 = blockIdx.x * TN;                                                   \
    int arow = tid >> 2, kq = tid & 3;                                          \
    int brow0 = tid >> 2, brow1 = (tid >> 2) + 64;                              \
    float acc[8][4] = {};                                                       \
    float4 rA, rB0, rB1;                                                        \
    {                                                                           \
        int k = (KSTART) + kq * 4;                                              \
        rA = AFETCH4(arow, k);                                                  \
        rB0 = WFETCH4(brow0, k);                                                \
        rB1 = WFETCH4(brow1, k);                                                \
    }                                                                           \
    As[0][kq * 4 + 0][arow] = rA.x;  As[0][kq * 4 + 1][arow] = rA.y;            \
    As[0][kq * 4 + 2][arow] = rA.z;  As[0][kq * 4 + 3][arow] = rA.w;            \
    Ws[0][kq * 4 + 0][brow0] = rB0.x; Ws[0][kq * 4 + 1][brow0] = rB0.y;         \
    Ws[0][kq * 4 + 2][brow0] = rB0.z; Ws[0][kq * 4 + 3][brow0] = rB0.w;         \
    Ws[0][kq * 4 + 0][brow1] = rB1.x; Ws[0][kq * 4 + 1][brow1] = rB1.y;         \
    Ws[0][kq * 4 + 2][brow1] = rB1.z; Ws[0][kq * 4 + 3][brow1] = rB1.w;         \
    __syncthreads();                                                            \
    for (int tile = 0; tile < (KTILES); ++tile) {                               \
        int buf = tile & 1;                                                     \
        bool more = (tile + 1) < (KTILES);                                      \
        if (more) {                                                             \
            int k = (KSTART) + (tile + 1) * TK + kq * 4;                        \
            rA = AFETCH4(arow, k);                                              \
            rB0 = WFETCH4(brow0, k);                                            \
            rB1 = WFETCH4(brow1, k);                                            \
        }                                                                       \
        _Pragma("unroll")                                                       \
        for (int kk = 0; kk < TK; ++kk) {                                       \
            float4 a0 = *(const float4*)&As[buf][kk][ty * 8];                   \
            float4 a1 = *(const float4*)&As[buf][kk][ty * 8 + 4];               \
            float4 wv = *(const float4*)&Ws[buf][kk][tx * 4];                   \
            float av[8] = {a0.x, a0.y, a0.z, a0.w, a1.x, a1.y, a1.z, a1.w};     \
            float wr[4] = {wv.x, wv.y, wv.z, wv.w};                             \
            _Pragma("unroll")                                                   \
            for (int i = 0; i < 8; ++i)                                         \
                _Pragma("unroll")                                               \
                for (int j = 0; j < 4; ++j) acc[i][j] += av[i] * wr[j];         \
        }                                                                       \
        __syncthreads();                                                        \
        if (more) {                                                             \
            int nb = buf ^ 1;                                                   \
            As[nb][kq * 4 + 0][arow] = rA.x;  As[nb][kq * 4 + 1][arow] = rA.y;  \
            As[nb][kq * 4 + 2][arow] = rA.z;  As[nb][kq * 4 + 3][arow] = rA.w;  \
            Ws[nb][kq * 4 + 0][brow0] = rB0.x; Ws[nb][kq * 4 + 1][brow0] = rB0.y;\
            Ws[nb][kq * 4 + 2][brow0] = rB0.z; Ws[nb][kq * 4 + 3][brow0] = rB0.w;\
            Ws[nb][kq * 4 + 0][brow1] = rB1.x; Ws[nb][kq * 4 + 1][brow1] = rB1.y;\
            Ws[nb][kq * 4 + 2][brow1] = rB1.z; Ws[nb][kq * 4 + 3][brow1] = rB1.w;\
            __syncthreads();                                                    \
        }                                                                       \
    }

// ---------------- sort / layout detect ----------------
__global__ void k_sort(const int* __restrict__ y32, float* __restrict__ out, size_t cap) {
    __shared__ int len[BB];
    __shared__ int stride_s;
    int i = threadIdx.x;
    if (i == 0) {
        int odd = 0;
        for (int l = 0; l < LL; ++l) odd |= (y32[2 * l + 1] != 0);
        stride_s = odd ? 1 : 2;
        g_ystride = stride_s;
    }
    __syncthreads();
    int stride = stride_s;
    if (i < BB) {
        int c = 0;
        for (int l = 0; l < LL; ++l) c += (y32[(i * LL + l) * stride] != 0);
        len[i] = c;
    }
    __syncthreads();
    if (i < BB) {
        int r = 0;
        for (int j = 0; j < BB; ++j)
            r += (len[j] > len[i]) || (len[j] == len[i] && j < i);
        g_sidx[r] = i;
        g_dlen[r] = len[i] - 1;
        size_t base = PRED_SZ + ALPHA_SZ;
        if (base + r < cap)      out[base + r]      = (float)(len[i] - 1);
        if (base + BB + r < cap) out[base + BB + r] = (float)i;
    }
}

// ---------------- sorted encoder -> fp16 copy ----------------
__global__ void k_ench(const float* __restrict__ enc) {
    int b = blockIdx.x, p = blockIdx.y;
    const float* src = enc + ((size_t)g_sidx[b] * PP + p) * ENC;
    __half2* dst = (__half2*)(g_ench + ((size_t)b * PP + p) * ENC);
    int i = threadIdx.x;   // 256 threads, 4 elems each pass
    #pragma unroll
    for (int it = 0; it < 2; ++it) {
        int e = (i + it * 256) * 4;
        float4 v = LD4(src[e]);
        dst[e >> 1]       = __floats2half2_rn(v.x, v.y);
        dst[(e >> 1) + 1] = __floats2half2_rn(v.z, v.w);
    }
}

// ---------------- mean over P ----------------
__global__ void k_mean(const float* __restrict__ enc) {
    int b = blockIdx.x;
    int e = blockIdx.y * 256 + threadIdx.x;
    const float* base = enc + (size_t)g_sidx[b] * PP * ENC + e;
    float s = 0.f;
    #pragma unroll 8
    for (int p = 0; p < PP; ++p) s += base[p * ENC];
    g_mean[b * ENC + e] = s * (1.0f / PP);
}

// ---------------- init h0/c0 GEMM + reduce ----------------
__global__ __launch_bounds__(256) void k_init_gemm(const float* __restrict__ ihW,
                                                   const float* __restrict__ icW) {
    int z = blockIdx.z;
#define A_INIT(row, k) LD4(g_mean[(row) * ENC + (k)])
#define W_INIT(row, k) ((n0 + (row)) < HH ? LD4(ihW[(n0 + (row)) * ENC + (k)]) \
                                          : LD4(icW[(n0 + (row) - HH) * ENC + (k)]))
    GEMM2_BODY(A_INIT, W_INIT, z * (ENC / SP_INIT), (ENC / SP_INIT) / TK);
    float* P = g_initP + (size_t)z * BB * 1024;
    #pragma unroll
    for (int i = 0; i < 8; ++i) {
        int m = ty * 8 + i;
        *(float4*)&P[m * 1024 + n0 + tx * 4] =
            make_float4(acc[i][0], acc[i][1], acc[i][2], acc[i][3]);
    }
#undef A_INIT
#undef W_INIT
}

__global__ void k_init_red(const float* __restrict__ ihb, const float* __restrict__ icb) {
    int b = blockIdx.x, n = threadIdx.x;    // 1024 threads
    float s = (n < HH) ? ihb[n] : icb[n - HH];
    #pragma unroll
    for (int z = 0; z < SP_INIT; ++z) s += g_initP[((size_t)z * BB + b) * 1024 + n];
    if (n < HH) g_h[b * HH + n] = s;
    else        g_c[b * HH + (n - HH)] = s;
}

// ---------------- att1 (PIPE2): enc_sorted @ e2aW^T, 128x128 tiles ----------------
__global__ __launch_bounds__(256) void k_att1_mma(const float* __restrict__ enc,
                                                  const float* __restrict__ e2aW) {
    __shared__ int rowOff[128];
    int m0 = blockIdx.y * 128;
    if (threadIdx.x < 128) {
        int m = m0 + threadIdx.x;
        int b = m / PP, p = m % PP;
        rowOff[threadIdx.x] = (g_sidx[b] * PP + p) * ENC;
    }
    __syncthreads();
#define AF_A1 { int kf = 2 * kc2 + q2 * 16; \
                FETCH16(enc + rowOff[r2] + kf, rAu0, rAu1, rAv0, rAv1); }
#define BF_A1 { int kf = 2 * kc2 + q2 * 16; \
                FETCH16(e2aW + (size_t)(n0 + r2) * ENC + kf, rBu0, rBu1, rBv0, rBv1); }
    MMA_PIPE2(AF_A1, BF_A1, ENC / 32, 1);
    #pragma unroll
    for (int s = 0; s < 2; ++s)
        #pragma unroll
        for (int nt = 0; nt < 8; ++nt) {
            int col = n0 + nh * 64 + nt * 8 + 2 * tig;
            int r0 = m0 + mw2 * 32 + s * 16 + g, r1 = r0 + 8;
            g_att1[(size_t)r0 * AA + col]     = c[s][nt][0];
            g_att1[(size_t)r0 * AA + col + 1] = c[s][nt][1];
            g_att1[(size_t)r1 * AA + col]     = c[s][nt][2];
            g_att1[(size_t)r1 * AA + col + 1] = c[s][nt][3];
        }
#undef AF_A1
#undef BF_A1
}

// ---------------- hW (MMA): h @ [h2aW;fbW]^T -> att2F + gateF(sigmoid) ----------------
__global__ __launch_bounds__(256) void k_hw(const float* __restrict__ h2aW,
                                            const float* __restrict__ fbW,
                                            const float* __restrict__ fbb, int t) {
    MMA_PIPE(AFETCH_FLT(g_h + ar * HH + kf),
             BFETCH_FLT((n0 + br) < AA ? h2aW + (size_t)(n0 + br) * HH + kf
                                       : fbW + (size_t)(n0 + br - AA) * HH + kf),
             0, HH / 32, t);
    #pragma unroll
    for (int nt = 0; nt < 8; ++nt) {
        int col = n0 + nh * 64 + nt * 8 + 2 * tig;
        int r0 = mw * 16 + g, r1 = r0 + 8;
        float v[4] = {c[nt][0], c[nt][1], c[nt][2], c[nt][3]};
        int rr[4] = {r0, r0, r1, r1};
        int cc[4] = {col, col + 1, col, col + 1};
        #pragma unroll
        for (int q = 0; q < 4; ++q) {
            if (cc[q] < AA) g_att2F[rr[q] * AA + cc[q]] = v[q];
            else {
                int e = cc[q] - AA;
                g_gateF[rr[q] * ENC + e] = sigmf(v[q] + fbb[e]);
            }
        }
    }
}

// ---------------- fused score + softmax + ctx (fp16 enc) ----------------
__global__ __launch_bounds__(512) void k_score_ctx(const float* __restrict__ attW,
                                                   const float* __restrict__ attb,
                                                   float* __restrict__ out, size_t cap, int t) {
    __shared__ float a2[AA];
    __shared__ float aw[AA];
    __shared__ float sc[PP];
    __shared__ float al[PP];
    __shared__ float red[2];
    int b = blockIdx.x, tid = threadIdx.x;
    if (g_dlen[b] <= t) {
        for (int p = tid; p < PP; p += 512) {
            size_t idx = PRED_SZ + (size_t)(b * TT + t) * PP + p;
            if (idx < cap) out[idx] = 0.f;
        }
        return;
    }
    for (int i = tid; i < AA; i += 512) {
        a2[i] = g_att2F[b * AA + i];
        aw[i] = attW[i];
    }
    __syncthreads();
    int w = tid >> 5, lane = tid & 31;
    for (int p = w; p < PP; p += 16) {
        const float* base = g_att1 + (size_t)(b * PP + p) * AA;
        float s = 0.f;
        #pragma unroll 4
        for (int a0 = lane; a0 < AA; a0 += 32) {
            float v = base[a0] + a2[a0];
            s += fmaxf(v, 0.f) * aw[a0];
        }
        #pragma unroll
        for (int o = 16; o; o >>= 1) s += __shfl_down_sync(0xFFFFFFFFu, s, o);
        if (lane == 0) sc[p] = s + attb[0];
    }
    __syncthreads();
    if (w == 0) {
        float mx = -1e30f;
        for (int p = lane; p < PP; p += 32) mx = fmaxf(mx, sc[p]);
        #pragma unroll
        for (int o = 16; o; o >>= 1) mx = fmaxf(mx, __shfl_xor_sync(0xFFFFFFFFu, mx, o));
        float sm = 0.f;
        for (int p = lane; p < PP; p += 32) sm += expf(sc[p] - mx);
        #pragma unroll
        for (int o = 16; o; o >>= 1) sm += __shfl_xor_sync(0xFFFFFFFFu, sm, o);
        if (lane == 0) { red[0] = mx; red[1] = 1.0f / sm; }
    }
    __syncthreads();
    float mx = red[0], inv = red[1];
    for (int p = tid; p < PP; p += 512) {
        float a = expf(sc[p] - mx) * inv;
        al[p] = a;
        size_t idx = PRED_SZ + (size_t)(b * TT + t) * PP + p;
        if (idx < cap) out[idx] = a;
    }
    __syncthreads();
    // ctx: thread handles 4 consecutive e (fp16 enc, L2-resident)
    int e0 = tid * 4;
    const __half2* base = (const __half2*)(g_ench + (size_t)b * PP * ENC + e0);
    float s0 = 0.f, s1 = 0.f, s2 = 0.f, s3 = 0.f;
    #pragma unroll 4
    for (int p = 0; p < PP; ++p) {
        const __half2* rp = base + p * (ENC / 2);
        float2 f01 = __half22float2(rp[0]);
        float2 f23 = __half22float2(rp[1]);
        float a = al[p];
        s0 += a * f01.x; s1 += a * f01.y;
        s2 += a * f23.x; s3 += a * f23.y;
    }
    float4 gt = LD4(g_gateF[b * ENC + e0]);
    *(float4*)&g_ctx[b * ENC + e0] =
        make_float4(gt.x * s0, gt.y * s1, gt.z * s2, gt.w * s3);
}

// ---------------- gates (MMA): [emb|ctx|h] @ [Wih;Whh]^T, K-split x8 ----------------
__global__ __launch_bounds__(256) void k_gates_mma(const int* __restrict__ y32,
                                                   const float* __restrict__ emb,
                                                   const float* __restrict__ Wih,
                                                   const float* __restrict__ Whh,
                                                   int t) {
    __shared__ int tokOff[64];
    if (threadIdx.x < 64) {
        int tok = y32[(g_sidx[threadIdx.x] * LL + t) * g_ystride];
        tok = max(0, min(tok, VV - 1));
        tokOff[threadIdx.x] = tok * EE;
    }
    __syncthreads();
    int z = blockIdx.z;
    MMA_PIPE(
        AFETCH_FLT(kf < EE ? emb + tokOff[ar] + kf
                   : kf < EE + ENC ? g_ctx + ar * ENC + (kf - EE)
                                   : g_h + ar * HH + (kf - EE - ENC)),
        BFETCH_FLT(kf < EE + ENC ? Wih + (size_t)(n0 + br) * (EE + ENC) + kf
                                 : Whh + (size_t)(n0 + br) * HH + (kf - EE - ENC)),
        z * 192, 12, t);
    float* P = g_gatesP + (size_t)z * BB * 4 * HH;
    #pragma unroll
    for (int nt = 0; nt < 8; ++nt) {
        int col = n0 + nh * 64 + nt * 8 + 2 * tig;
        int r0 = mw * 16 + g, r1 = r0 + 8;
        P[r0 * (4 * HH) + col]     = c[nt][0];
        P[r0 * (4 * HH) + col + 1] = c[nt][1];
        P[r1 * (4 * HH) + col]     = c[nt][2];
        P[r1 * (4 * HH) + col + 1] = c[nt][3];
    }
}

// ---------------- LSTM: reduce partials, update h/c, record h history ----------------
__global__ void k_lstm(const float* __restrict__ bih, const float* __restrict__ bhh, int t) {
    int b = blockIdx.x, j = threadIdx.x;   // 512 threads
    float* hall = g_hall + ((size_t)t * BB + b) * HH;
    if (g_dlen[b] <= t) {
        hall[j] = g_h[b * HH + j];
        return;
    }
    float gs[4];
    #pragma unroll
    for (int gI = 0; gI < 4; ++gI) {
        int n = gI * HH + j;
        float s = bih[n] + bhh[n];
        #pragma unroll
        for (int z = 0; z < SP_GT; ++z)
            s += g_gatesP[((size_t)z * BB + b) * (4 * HH) + n];
        gs[gI] = s;
    }
    float ig = sigmf(gs[0]);
    float fg = sigmf(gs[1]);
    float gg = tanhf(gs[2]);
    float og = sigmf(gs[3]);
    float cv = fg * g_c[b * HH + j] + ig * gg;
    g_c[b * HH + j] = cv;
    float h = og * tanhf(cv);
    g_h[b * HH + j] = h;
    hall[j] = h;
}

// ---------------- final logits (PIPE2): [1216,512] @ fcW^T, 128-row tiles ----------------
__global__ __launch_bounds__(256) void k_logits_fin(const float* __restrict__ fcW,
                                                    const float* __restrict__ fcb,
                                                    float* __restrict__ out, size_t cap) {
    int T0 = blockIdx.y;
#define AF_LG { int kf = 2 * kc2 + q2 * 16; \
                int gr = min(T0 * 128 + r2, TT * BB - 1); \
                FETCH16(g_hall + (size_t)gr * HH + kf, rAu0, rAu1, rAv0, rAv1); }
#define BF_LG { int kf = 2 * kc2 + q2 * 16; \
                FETCH16(fcW + (size_t)(n0 + r2) * HH + kf, rBu0, rBu1, rBv0, rBv1); }
    MMA_PIPE2(AF_LG, BF_LG, HH / 32,
              ({ int tw = T0 * 2 + (mw2 >> 1); int bw = (mw2 & 1) * 32;
                 (tw < TT) && (g_dlen[bw] > tw); }));
    #pragma unroll
    for (int s = 0; s < 2; ++s)
        #pragma unroll
        for (int nt = 0; nt < 8; ++nt) {
            int col = n0 + nh * 64 + nt * 8 + 2 * tig;
            int r0 = T0 * 128 + mw2 * 32 + s * 16 + g, r1 = r0 + 8;
            int t0 = r0 >> 6;
            if (t0 >= TT) continue;
            int b0 = r0 & 63, b1 = b0 + 8;
            bool act0 = g_dlen[b0] > t0, act1 = g_dlen[b1] > t0;
            size_t i00 = ((size_t)b0 * TT + t0) * VV + col;
            size_t i10 = ((size_t)b1 * TT + t0) * VV + col;
            if (i00 + 1 < cap) {
                out[i00]     = act0 ? c[s][nt][0] + fcb[col]     : 0.f;
                out[i00 + 1] = act0 ? c[s][nt][1] + fcb[col + 1] : 0.f;
            }
            if (i10 + 1 < cap) {
                out[i10]     = act1 ? c[s][nt][2] + fcb[col]     : 0.f;
                out[i10 + 1] = act1 ? c[s][nt][3] + fcb[col + 1] : 0.f;
            }
        }
#undef AF_LG
#undef BF_LG
}

// ---------------- launch ----------------
extern "C" void kernel_launch(void* const* d_in, const int* in_sizes, int n_in,
                              void* d_out, int out_size) {
    if (n_in < 19) return;
    const float* enc  = (const float*)d_in[0];
    const int*   y32  = (const int*)d_in[1];
    const float* emb  = (const float*)d_in[2];
    const float* e2aW = (const float*)d_in[3];
    const float* h2aW = (const float*)d_in[4];
    const float* attW = (const float*)d_in[5];
    const float* attb = (const float*)d_in[6];
    const float* fbW  = (const float*)d_in[7];
    const float* fbb  = (const float*)d_in[8];
    const float* Wih  = (const float*)d_in[9];
    const float* bih  = (const float*)d_in[10];
    const float* Whh  = (const float*)d_in[11];
    const float* bhh  = (const float*)d_in[12];
    const float* fcW  = (const float*)d_in[13];
    const float* fcb  = (const float*)d_in[14];
    const float* ihW  = (const float*)d_in[15];
    const float* ihb  = (const float*)d_in[16];
    const float* icW  = (const float*)d_in[17];
    const float* icb  = (const float*)d_in[18];

    float* out = (float*)d_out;
    size_t cap = (size_t)out_size;

    static int attr_done = 0;
    if (!attr_done) {
        cudaFuncSetAttribute(k_att1_mma,   cudaFuncAttributeMaxDynamicSharedMemorySize, SM2_BYTES);
        cudaFuncSetAttribute(k_logits_fin, cudaFuncAttributeMaxDynamicSharedMemorySize, SM2_BYTES);
        cudaFuncSetAttribute(k_hw,         cudaFuncAttributeMaxDynamicSharedMemorySize, SM_BYTES);
        cudaFuncSetAttribute(k_gates_mma,  cudaFuncAttributeMaxDynamicSharedMemorySize, SM_BYTES);
        attr_done = 1;
    }

    // preamble
    k_sort<<<1, 64>>>(y32, out, cap);
    k_ench<<<dim3(BB, PP), 256>>>(enc);
    k_mean<<<dim3(BB, ENC / 256), 256>>>(enc);
    k_init_gemm<<<dim3(1024 / TN, 1, SP_INIT), 256>>>(ihW, icW);
    k_init_red<<<BB, 1024>>>(ihb, icb);
    k_att1_mma<<<dim3(AA / 128, (BB * PP) / 128), 256, SM2_BYTES>>>(enc, e2aW);

    // recurrent loop (4 kernels per step)
    for (int t = 0; t < TT; ++t) {
        k_hw<<<2560 / 128, 256, SM_BYTES>>>(h2aW, fbW, fbb, t);
        k_score_ctx<<<BB, 512>>>(attW, attb, out, cap, t);
        k_gates_mma<<<dim3((4 * HH) / 128, 1, SP_GT), 256, SM_BYTES>>>(y32, emb, Wih, Whh, t);
        k_lstm<<<BB, HH>>>(bih, bhh, t);
    }

    // one big deferred vocabulary projection (fcW read once), 128-row tiles
    k_logits_fin<<<dim3(VV / 128, (TT * BB + 127) / 128), 256, SM2_BYTES>>>(fcW, fcb, out, cap);
}